// round 2
// baseline (speedup 1.0000x reference)
#include <cuda_runtime.h>
#include <math.h>
#include <stdint.h>

#define BATCH 8
#define SEQ   1024
#define DIMC  768
#define NH    12
#define HD    64
#define BH    (BATCH*NH)        // 96
#define NN    (SEQ*SEQ)         // 1048576
#define KTH   524288u
#define NBINS 32768

// ---------------- scratch (no cudaMalloc allowed) ----------------
__device__ float g_Q[(size_t)BH*SEQ*HD];
__device__ float g_K[(size_t)BH*SEQ*HD];
__device__ float g_V[(size_t)BH*SEQ*HD];
__device__ float g_O[(size_t)BH*SEQ*HD];
__device__ float g_Pfallback[(size_t)BH*NN];   // used only if d_out doesn't include attn
__device__ unsigned g_hist1[(size_t)BH*NBINS];
__device__ unsigned g_hist2[(size_t)BH*NBINS];
__device__ unsigned g_bucket[BH];
__device__ unsigned g_rank[BH];
__device__ float    g_thresh[BH];

// ---------------- 0: zero histograms ----------------
__global__ void zero_hists() {
    size_t n = (size_t)BH*NBINS;
    for (size_t i = blockIdx.x*(size_t)blockDim.x + threadIdx.x; i < n; i += (size_t)gridDim.x*blockDim.x) {
        g_hist1[i] = 0u; g_hist2[i] = 0u;
    }
}

// ---------------- 1: QKV GEMM  C[i,j]=x[i,:]·w_qkv[j,:]+b, split into Q(*0.125)/K/V [B,H,N,hd]
__global__ void __launch_bounds__(256,2) qkv_gemm(const float* __restrict__ X,
                                                  const float* __restrict__ W,
                                                  const float* __restrict__ bias) {
    __shared__ float As[8][128];
    __shared__ float Bs[8][128];
    const int tid = threadIdx.x;
    const int bn = blockIdx.x, bm = blockIdx.y;
    const int arow = tid >> 1, acol = (tid & 1) << 2;
    const int tx = tid & 15, ty = tid >> 4;

    const float* Aptr = X + (size_t)(bm*128 + arow)*DIMC + acol;
    const float* Bptr = W + (size_t)(bn*128 + arow)*DIMC + acol;

    float acc[8][8];
    #pragma unroll
    for (int i = 0; i < 8; i++)
        #pragma unroll
        for (int j = 0; j < 8; j++) acc[i][j] = 0.f;

    for (int kt = 0; kt < DIMC/8; kt++) {
        float4 a4 = *(const float4*)(Aptr + kt*8);
        float4 b4 = *(const float4*)(Bptr + kt*8);
        __syncthreads();
        As[acol+0][arow]=a4.x; As[acol+1][arow]=a4.y; As[acol+2][arow]=a4.z; As[acol+3][arow]=a4.w;
        Bs[acol+0][arow]=b4.x; Bs[acol+1][arow]=b4.y; Bs[acol+2][arow]=b4.z; Bs[acol+3][arow]=b4.w;
        __syncthreads();
        #pragma unroll
        for (int kk = 0; kk < 8; kk++) {
            float4 a0 = *(const float4*)&As[kk][ty*8];
            float4 a1 = *(const float4*)&As[kk][ty*8+4];
            float4 b0 = *(const float4*)&Bs[kk][tx*8];
            float4 b1 = *(const float4*)&Bs[kk][tx*8+4];
            float rm[8] = {a0.x,a0.y,a0.z,a0.w,a1.x,a1.y,a1.z,a1.w};
            float rn[8] = {b0.x,b0.y,b0.z,b0.w,b1.x,b1.y,b1.z,b1.w};
            #pragma unroll
            for (int i = 0; i < 8; i++)
                #pragma unroll
                for (int j = 0; j < 8; j++) acc[i][j] += rm[i]*rn[j];
        }
    }
    #pragma unroll
    for (int i = 0; i < 8; i++) {
        int gi = bm*128 + ty*8 + i;
        int b = gi >> 10, n = gi & 1023;
        #pragma unroll
        for (int j = 0; j < 8; j++) {
            int gj = bn*128 + tx*8 + j;
            float val = acc[i][j] + bias[gj];
            int t = gj / DIMC;
            int r = gj - t*DIMC;
            int h = r >> 6, d = r & 63;
            size_t dst = (((size_t)b*NH + h)*SEQ + n)*HD + d;
            if (t == 0)      g_Q[dst] = val * 0.125f;   // hd^-0.5
            else if (t == 1) g_K[dst] = val;
            else             g_V[dst] = val;
        }
    }
}

// ---------------- 2: scores + log(token_scales) + softmax -> P ----------------
// CTA = 32 rows of one (b,h). smem: S[32][1024] + Q[32][64] + Ktile[128][68] + lts[1024]
#define K2_SMEM ((32*1024 + 32*64 + 128*68 + 1024) * 4)
__global__ void __launch_bounds__(256) softmax_kernel(const float* __restrict__ ts,
                                                      float* __restrict__ P) {
    extern __shared__ float sm[];
    float* Ssm = sm;                      // 32*1024
    float* Qs  = sm + 32*1024;            // 32*64
    float* Ks  = Qs + 32*64;              // 128*68 (padded)
    float* lts = Ks + 128*68;             // 1024

    const int head = blockIdx.y, rb = blockIdx.x;
    const int b = head / NH;
    const int tid = threadIdx.x;
    const int lane = tid & 31, w = tid >> 5;

    const float* Qg = g_Q + ((size_t)head*SEQ + rb*32)*HD;
    for (int v = tid; v < 32*64/4; v += 256)
        ((float4*)Qs)[v] = ((const float4*)Qg)[v];
    for (int m = tid; m < SEQ; m += 256)
        lts[m] = logf(ts[b*SEQ + m]);

    const int r0 = w*4;
    for (int ct = 0; ct < 8; ct++) {
        const float* Kg = g_K + ((size_t)head*SEQ + ct*128)*HD;
        __syncthreads();
        for (int v = tid; v < 128*16; v += 256) {   // 2048 float4
            int row = v >> 4, c4 = (v & 15) << 2;
            *(float4*)(Ks + row*68 + c4) = *(const float4*)(Kg + row*64 + c4);
        }
        __syncthreads();
        float acc[4][4];
        #pragma unroll
        for (int i = 0; i < 4; i++)
            #pragma unroll
            for (int j = 0; j < 4; j++) acc[i][j] = 0.f;
        #pragma unroll
        for (int d0 = 0; d0 < 64; d0 += 4) {
            float4 kf[4];
            #pragma unroll
            for (int c = 0; c < 4; c++) kf[c] = *(const float4*)(Ks + (lane + 32*c)*68 + d0);
            #pragma unroll
            for (int ri = 0; ri < 4; ri++) {
                float4 q = *(const float4*)(Qs + (r0+ri)*64 + d0);
                #pragma unroll
                for (int c = 0; c < 4; c++)
                    acc[ri][c] += q.x*kf[c].x + q.y*kf[c].y + q.z*kf[c].z + q.w*kf[c].w;
            }
        }
        #pragma unroll
        for (int ri = 0; ri < 4; ri++)
            #pragma unroll
            for (int c = 0; c < 4; c++)
                Ssm[(r0+ri)*1024 + ct*128 + lane + 32*c] = acc[ri][c];
    }
    __syncthreads();

    const size_t Pbase = (size_t)head*NN + (size_t)rb*32*1024;
    for (int ri = 0; ri < 4; ri++) {
        int r = r0 + ri;
        float* row = Ssm + (size_t)r*1024;
        float mx = -1e30f;
        for (int m = lane; m < 1024; m += 32) mx = fmaxf(mx, row[m] + lts[m]);
        #pragma unroll
        for (int o = 16; o > 0; o >>= 1) mx = fmaxf(mx, __shfl_xor_sync(0xffffffffu, mx, o));
        float sum = 0.f;
        for (int m = lane; m < 1024; m += 32) {
            float e = __expf(row[m] + lts[m] - mx);
            row[m] = e; sum += e;
        }
        #pragma unroll
        for (int o = 16; o > 0; o >>= 1) sum += __shfl_xor_sync(0xffffffffu, sum, o);
        float inv = 1.0f / sum;
        float* Pr = P + Pbase + (size_t)r*1024;
        for (int m = lane; m < 1024; m += 32) Pr[m] = row[m] * inv;
    }
}

// ---------------- 3/5: histograms (warp-aggregated smem atomics) ----------------
__global__ void __launch_bounds__(256) hist1_kernel(const float* __restrict__ P) {
    extern __shared__ unsigned sh[];
    for (int i = threadIdx.x; i < NBINS; i += 256) sh[i] = 0u;
    __syncthreads();
    const int head = blockIdx.y;
    const float* base = P + (size_t)head*NN + (size_t)blockIdx.x*(NN/8);
    const int lane = threadIdx.x & 31;
    for (int i = threadIdx.x; i < NN/8; i += 256) {
        unsigned bits = __float_as_uint(base[i]);
        unsigned bin = bits >> 15;
        if (bin >= NBINS) bin = NBINS-1;
        unsigned mask = __match_any_sync(0xffffffffu, bin);
        if (lane == (__ffs(mask)-1)) atomicAdd(&sh[bin], (unsigned)__popc(mask));
    }
    __syncthreads();
    unsigned* gh = g_hist1 + (size_t)head*NBINS;
    for (int i = threadIdx.x; i < NBINS; i += 256) {
        unsigned c = sh[i];
        if (c) atomicAdd(&gh[i], c);
    }
}

__global__ void __launch_bounds__(256) hist2_kernel(const float* __restrict__ P) {
    extern __shared__ unsigned sh[];
    for (int i = threadIdx.x; i < NBINS; i += 256) sh[i] = 0u;
    __syncthreads();
    const int head = blockIdx.y;
    const unsigned bucket = g_bucket[head];
    const float* base = P + (size_t)head*NN + (size_t)blockIdx.x*(NN/8);
    const int lane = threadIdx.x & 31;
    for (int i = threadIdx.x; i < NN/8; i += 256) {
        unsigned bits = __float_as_uint(base[i]);
        unsigned top = bits >> 15;
        if (top >= NBINS) top = NBINS-1;
        if (top == bucket) {
            unsigned bin = bits & 0x7FFFu;
            unsigned am = __activemask();
            unsigned mask = __match_any_sync(am, bin);
            if (lane == (__ffs(mask)-1)) atomicAdd(&sh[bin], (unsigned)__popc(mask));
        }
    }
    __syncthreads();
    unsigned* gh = g_hist2 + (size_t)head*NBINS;
    for (int i = threadIdx.x; i < NBINS; i += 256) {
        unsigned c = sh[i];
        if (c) atomicAdd(&gh[i], c);
    }
}

// ---------------- 4/6: select bucket / exact threshold ----------------
__global__ void __launch_bounds__(256) select1_kernel() {
    const int head = blockIdx.x, tid = threadIdx.x;
    __shared__ unsigned part[256];
    __shared__ unsigned excl[256];
    const unsigned* h = g_hist1 + (size_t)head*NBINS;
    unsigned s = 0;
    for (int j = 0; j < 128; j++) s += h[tid*128 + j];
    part[tid] = s;
    __syncthreads();
    if (tid == 0) {
        unsigned c = 0;
        for (int i = 0; i < 256; i++) { excl[i] = c; c += part[i]; }
    }
    __syncthreads();
    unsigned lo = excl[tid], hi = lo + part[tid];
    if (lo < KTH && KTH <= hi) {
        unsigned c = lo;
        for (int j = 0; j < 128; j++) {
            unsigned cnt = h[tid*128 + j];
            if (c + cnt >= KTH) { g_bucket[head] = tid*128 + j; g_rank[head] = KTH - c; break; }
            c += cnt;
        }
    }
}

__global__ void __launch_bounds__(256) select2_kernel() {
    const int head = blockIdx.x, tid = threadIdx.x;
    __shared__ unsigned part[256];
    __shared__ unsigned excl[256];
    const unsigned target = g_rank[head];
    const unsigned* h = g_hist2 + (size_t)head*NBINS;
    unsigned s = 0;
    for (int j = 0; j < 128; j++) s += h[tid*128 + j];
    part[tid] = s;
    __syncthreads();
    if (tid == 0) {
        unsigned c = 0;
        for (int i = 0; i < 256; i++) { excl[i] = c; c += part[i]; }
    }
    __syncthreads();
    unsigned lo = excl[tid], hi = lo + part[tid];
    if (lo < target && target <= hi) {
        unsigned c = lo;
        for (int j = 0; j < 128; j++) {
            unsigned cnt = h[tid*128 + j];
            if (c + cnt >= target) {
                unsigned bits = (g_bucket[head] << 15) | (unsigned)(tid*128 + j);
                g_thresh[head] = __uint_as_float(bits);
                break;
            }
            c += cnt;
        }
    }
}

// ---------------- 7: sparsify P in place + O = P' @ V ----------------
__global__ void __launch_bounds__(256) av_kernel(float* __restrict__ P) {
    __shared__ float Ps[32*132];   // [k][m] transposed, padded
    __shared__ float Vs[32*68];    // [k][d] padded
    const int head = blockIdx.y, rb = blockIdx.x;
    const int tid = threadIdx.x;
    const int tx = tid & 15, ty = tid >> 4;
    const float t = g_thresh[head];
    float* Pbase = P + (size_t)head*NN + (size_t)rb*128*1024;
    const float* Vbase = g_V + (size_t)head*SEQ*HD;

    float acc[8][4];
    #pragma unroll
    for (int i = 0; i < 8; i++)
        #pragma unroll
        for (int j = 0; j < 4; j++) acc[i][j] = 0.f;

    for (int kb = 0; kb < 32; kb++) {
        __syncthreads();
        #pragma unroll
        for (int p = 0; p < 4; p++) {
            int v = tid + p*256;
            int r = v >> 3, c4 = (v & 7) << 2;
            float* gp = Pbase + (size_t)r*1024 + kb*32 + c4;
            float4 x = *(float4*)gp;
            x.x = (x.x < t) ? 0.f : x.x;
            x.y = (x.y < t) ? 0.f : x.y;
            x.z = (x.z < t) ? 0.f : x.z;
            x.w = (x.w < t) ? 0.f : x.w;
            *(float4*)gp = x;                         // sparsified attn output
            Ps[(c4+0)*132 + r] = x.x;
            Ps[(c4+1)*132 + r] = x.y;
            Ps[(c4+2)*132 + r] = x.z;
            Ps[(c4+3)*132 + r] = x.w;
        }
        #pragma unroll
        for (int p = 0; p < 2; p++) {
            int v = tid + p*256;
            int kk = v >> 4, c4 = (v & 15) << 2;
            *(float4*)(Vs + kk*68 + c4) = *(const float4*)(Vbase + (size_t)(kb*32+kk)*64 + c4);
        }
        __syncthreads();
        #pragma unroll
        for (int kk = 0; kk < 32; kk++) {
            float4 m0 = *(const float4*)(Ps + kk*132 + ty*8);
            float4 m1 = *(const float4*)(Ps + kk*132 + ty*8 + 4);
            float4 n0 = *(const float4*)(Vs + kk*68 + tx*4);
            float rm[8] = {m0.x,m0.y,m0.z,m0.w,m1.x,m1.y,m1.z,m1.w};
            float rn[4] = {n0.x,n0.y,n0.z,n0.w};
            #pragma unroll
            for (int i = 0; i < 8; i++)
                #pragma unroll
                for (int j = 0; j < 4; j++) acc[i][j] += rm[i]*rn[j];
        }
    }
    float* Obase = g_O + (size_t)head*SEQ*HD + (size_t)(rb*128 + ty*8)*64 + tx*4;
    #pragma unroll
    for (int i = 0; i < 8; i++) {
        float4 o = make_float4(acc[i][0], acc[i][1], acc[i][2], acc[i][3]);
        *(float4*)(Obase + (size_t)i*64) = o;
    }
}

// ---------------- 8: out = O_gathered @ w_proj^T + b_proj ----------------
__global__ void __launch_bounds__(256,2) proj_gemm(const float* __restrict__ W,
                                                   const float* __restrict__ bias,
                                                   float* __restrict__ out) {
    __shared__ float As[8][128];
    __shared__ float Bs[8][128];
    const int tid = threadIdx.x;
    const int bn = blockIdx.x, bm = blockIdx.y;
    const int arow = tid >> 1, acol = (tid & 1) << 2;
    const int tx = tid & 15, ty = tid >> 4;

    const int gi = bm*128 + arow;
    const int b = gi >> 10, n = gi & 1023;
    const float* Bptr = W + (size_t)(bn*128 + arow)*DIMC + acol;

    float acc[8][8];
    #pragma unroll
    for (int i = 0; i < 8; i++)
        #pragma unroll
        for (int j = 0; j < 8; j++) acc[i][j] = 0.f;

    for (int kt = 0; kt < DIMC/8; kt++) {
        int j0 = kt*8 + acol;
        int h = j0 >> 6, d = j0 & 63;
        float4 a4 = *(const float4*)(g_O + (((size_t)b*NH + h)*SEQ + n)*HD + d);
        float4 b4 = *(const float4*)(Bptr + kt*8);
        __syncthreads();
        As[acol+0][arow]=a4.x; As[acol+1][arow]=a4.y; As[acol+2][arow]=a4.z; As[acol+3][arow]=a4.w;
        Bs[acol+0][arow]=b4.x; Bs[acol+1][arow]=b4.y; Bs[acol+2][arow]=b4.z; Bs[acol+3][arow]=b4.w;
        __syncthreads();
        #pragma unroll
        for (int kk = 0; kk < 8; kk++) {
            float4 a0 = *(const float4*)&As[kk][ty*8];
            float4 a1 = *(const float4*)&As[kk][ty*8+4];
            float4 b0 = *(const float4*)&Bs[kk][tx*8];
            float4 b1 = *(const float4*)&Bs[kk][tx*8+4];
            float rm[8] = {a0.x,a0.y,a0.z,a0.w,a1.x,a1.y,a1.z,a1.w};
            float rn[8] = {b0.x,b0.y,b0.z,b0.w,b1.x,b1.y,b1.z,b1.w};
            #pragma unroll
            for (int i = 0; i < 8; i++)
                #pragma unroll
                for (int j = 0; j < 8; j++) acc[i][j] += rm[i]*rn[j];
        }
    }
    #pragma unroll
    for (int i = 0; i < 8; i++) {
        int oi = bm*128 + ty*8 + i;
        #pragma unroll
        for (int j = 0; j < 8; j++) {
            int oj = bn*128 + tx*8 + j;
            out[(size_t)oi*DIMC + oj] = acc[i][j] + bias[oj];
        }
    }
}

// ---------------- launch ----------------
extern "C" void kernel_launch(void* const* d_in, const int* in_sizes, int n_in,
                              void* d_out, int out_size) {
    const float* x     = (const float*)d_in[0];
    const float* ts    = (const float*)d_in[1];
    const float* wqkv  = (const float*)d_in[2];
    const float* bqkv  = (const float*)d_in[3];
    const float* wproj = (const float*)d_in[4];
    const float* bproj = (const float*)d_in[5];
    float* out = (float*)d_out;

    const size_t out_elems  = (size_t)BATCH*SEQ*DIMC;        // 6291456
    const size_t attn_elems = (size_t)BH*NN;                 // 100663296
    float* P;
    if ((size_t)out_size >= out_elems + attn_elems) {
        P = out + out_elems;            // attn is part of the output tuple
    } else {
        cudaGetSymbolAddress((void**)&P, g_Pfallback);
    }

    cudaFuncSetAttribute(softmax_kernel, cudaFuncAttributeMaxDynamicSharedMemorySize, K2_SMEM);
    cudaFuncSetAttribute(hist1_kernel,  cudaFuncAttributeMaxDynamicSharedMemorySize, NBINS*4);
    cudaFuncSetAttribute(hist2_kernel,  cudaFuncAttributeMaxDynamicSharedMemorySize, NBINS*4);

    zero_hists<<<1024, 256>>>();
    qkv_gemm<<<dim3(2304/128, 8192/128), 256>>>(x, wqkv, bqkv);
    softmax_kernel<<<dim3(32, 96), 256, K2_SMEM>>>(ts, P);
    hist1_kernel<<<dim3(8, 96), 256, NBINS*4>>>(P);
    select1_kernel<<<96, 256>>>();
    hist2_kernel<<<dim3(8, 96), 256, NBINS*4>>>(P);
    select2_kernel<<<96, 256>>>();
    av_kernel<<<dim3(8, 96), 256>>>(P);
    proj_gemm<<<dim3(768/128, 8192/128), 256>>>(wproj, bproj, out);
}

// round 3
// speedup vs baseline: 1.3631x; 1.3631x over previous
#include <cuda_runtime.h>
#include <math.h>
#include <stdint.h>

#define BATCH 8
#define SEQ   1024
#define DIMC  768
#define NH    12
#define HD    64
#define BH    (BATCH*NH)        // 96
#define NN    (SEQ*SEQ)         // 1048576
#define KTH   524288u
#define NBINS 32768

// ---------------- scratch (no cudaMalloc allowed) ----------------
__device__ float g_Q[(size_t)BH*SEQ*HD];
__device__ float g_K[(size_t)BH*SEQ*HD];
__device__ float g_V[(size_t)BH*SEQ*HD];
__device__ float g_O[(size_t)BH*SEQ*HD];
__device__ float g_partial[(size_t)BH*SEQ*8];   // per-row, per-column-tile exp sums
__device__ float g_Pfallback[(size_t)BH*NN];
__device__ unsigned g_hist1[(size_t)BH*NBINS];
__device__ unsigned g_hist2[(size_t)BH*NBINS];
__device__ unsigned g_bucket[BH];
__device__ unsigned g_rank[BH];
__device__ float    g_thresh[BH];

// ---------------- 0: zero histograms ----------------
__global__ void zero_hists() {
    size_t n = (size_t)BH*NBINS;
    for (size_t i = blockIdx.x*(size_t)blockDim.x + threadIdx.x; i < n; i += (size_t)gridDim.x*blockDim.x) {
        g_hist1[i] = 0u; g_hist2[i] = 0u;
    }
}

// ---------------- 1: QKV GEMM (BK=16, register-prefetch double buffer) ----------------
__global__ void __launch_bounds__(256,2) qkv_gemm(const float* __restrict__ X,
                                                  const float* __restrict__ W,
                                                  const float* __restrict__ bias) {
    __shared__ float As[16][132];
    __shared__ float Bs[16][132];
    const int tid = threadIdx.x;
    const int bn = blockIdx.x, bm = blockIdx.y;
    const int tx = tid & 15, ty = tid >> 4;

    const float* Aptr = X + (size_t)(bm*128)*DIMC;
    const float* Bptr = W + (size_t)(bn*128)*DIMC;

    float4 pa[2], pb[2];
    #pragma unroll
    for (int p = 0; p < 2; p++) {
        int f = tid + p*256; int r = f >> 2, kc = (f & 3) << 2;
        pa[p] = *(const float4*)(Aptr + (size_t)r*DIMC + kc);
        pb[p] = *(const float4*)(Bptr + (size_t)r*DIMC + kc);
    }

    float acc[8][8];
    #pragma unroll
    for (int i = 0; i < 8; i++)
        #pragma unroll
        for (int j = 0; j < 8; j++) acc[i][j] = 0.f;

    for (int kt = 0; kt < DIMC/16; kt++) {
        #pragma unroll
        for (int p = 0; p < 2; p++) {
            int f = tid + p*256; int r = f >> 2, kc = (f & 3) << 2;
            As[kc+0][r]=pa[p].x; As[kc+1][r]=pa[p].y; As[kc+2][r]=pa[p].z; As[kc+3][r]=pa[p].w;
            Bs[kc+0][r]=pb[p].x; Bs[kc+1][r]=pb[p].y; Bs[kc+2][r]=pb[p].z; Bs[kc+3][r]=pb[p].w;
        }
        __syncthreads();
        if (kt + 1 < DIMC/16) {
            #pragma unroll
            for (int p = 0; p < 2; p++) {
                int f = tid + p*256; int r = f >> 2, kc = (f & 3) << 2;
                pa[p] = *(const float4*)(Aptr + (size_t)r*DIMC + (kt+1)*16 + kc);
                pb[p] = *(const float4*)(Bptr + (size_t)r*DIMC + (kt+1)*16 + kc);
            }
        }
        #pragma unroll
        for (int kk = 0; kk < 16; kk++) {
            float4 a0 = *(const float4*)&As[kk][ty*8];
            float4 a1 = *(const float4*)&As[kk][ty*8+4];
            float4 b0 = *(const float4*)&Bs[kk][tx*8];
            float4 b1 = *(const float4*)&Bs[kk][tx*8+4];
            float rm[8] = {a0.x,a0.y,a0.z,a0.w,a1.x,a1.y,a1.z,a1.w};
            float rn[8] = {b0.x,b0.y,b0.z,b0.w,b1.x,b1.y,b1.z,b1.w};
            #pragma unroll
            for (int i = 0; i < 8; i++)
                #pragma unroll
                for (int j = 0; j < 8; j++) acc[i][j] += rm[i]*rn[j];
        }
        __syncthreads();
    }
    #pragma unroll
    for (int i = 0; i < 8; i++) {
        int gi = bm*128 + ty*8 + i;
        int b = gi >> 10, n = gi & 1023;
        #pragma unroll
        for (int j = 0; j < 8; j++) {
            int gj = bn*128 + tx*8 + j;
            float val = acc[i][j] + bias[gj];
            int t = gj / DIMC;
            int r = gj - t*DIMC;
            int h = r >> 6, d = r & 63;
            size_t dst = (((size_t)b*NH + h)*SEQ + n)*HD + d;
            if (t == 0)      g_Q[dst] = val * 0.125f;
            else if (t == 1) g_K[dst] = val;
            else             g_V[dst] = val;
        }
    }
}

// ---------------- 2: score GEMM + exp (max-free softmax numerator) ----------------
// P[r][c] = exp(q_r . k_c + log ts_c); per-CTA row partial sums -> g_partial (deterministic)
__global__ void __launch_bounds__(256,2) score_gemm(const float* __restrict__ ts,
                                                    float* __restrict__ P) {
    __shared__ float As[4*16][132>= 132?132:132]; // placeholder sizing avoided below
    // NOTE: actual arrays declared next (BK=16)
    __shared__ float Bs[16][132];
    __shared__ float lts[128];
    float (*Asr)[132] = (float(*)[132])As;   // use first 16 rows only

    const int head = blockIdx.z;
    const int b = head / NH;
    const int rb = blockIdx.y, cb = blockIdx.x;
    const int tid = threadIdx.x;
    const int tx = tid & 15, ty = tid >> 4;

    const float* Aptr = g_Q + (size_t)head*SEQ*HD + (size_t)(rb*128)*HD;
    const float* Bptr = g_K + (size_t)head*SEQ*HD + (size_t)(cb*128)*HD;

    if (tid < 128) lts[tid] = logf(ts[b*SEQ + cb*128 + tid]);

    float4 pa[2], pb[2];
    #pragma unroll
    for (int p = 0; p < 2; p++) {
        int f = tid + p*256; int r = f >> 2, kc = (f & 3) << 2;
        pa[p] = *(const float4*)(Aptr + (size_t)r*HD + kc);
        pb[p] = *(const float4*)(Bptr + (size_t)r*HD + kc);
    }

    float acc[8][8];
    #pragma unroll
    for (int i = 0; i < 8; i++)
        #pragma unroll
        for (int j = 0; j < 8; j++) acc[i][j] = 0.f;

    for (int kt = 0; kt < HD/16; kt++) {
        #pragma unroll
        for (int p = 0; p < 2; p++) {
            int f = tid + p*256; int r = f >> 2, kc = (f & 3) << 2;
            Asr[kc+0][r]=pa[p].x; Asr[kc+1][r]=pa[p].y; Asr[kc+2][r]=pa[p].z; Asr[kc+3][r]=pa[p].w;
            Bs[kc+0][r]=pb[p].x;  Bs[kc+1][r]=pb[p].y;  Bs[kc+2][r]=pb[p].z;  Bs[kc+3][r]=pb[p].w;
        }
        __syncthreads();
        if (kt + 1 < HD/16) {
            #pragma unroll
            for (int p = 0; p < 2; p++) {
                int f = tid + p*256; int r = f >> 2, kc = (f & 3) << 2;
                pa[p] = *(const float4*)(Aptr + (size_t)r*HD + (kt+1)*16 + kc);
                pb[p] = *(const float4*)(Bptr + (size_t)r*HD + (kt+1)*16 + kc);
            }
        }
        #pragma unroll
        for (int kk = 0; kk < 16; kk++) {
            float4 a0 = *(const float4*)&Asr[kk][ty*8];
            float4 a1 = *(const float4*)&Asr[kk][ty*8+4];
            float4 b0 = *(const float4*)&Bs[kk][tx*8];
            float4 b1 = *(const float4*)&Bs[kk][tx*8+4];
            float rm[8] = {a0.x,a0.y,a0.z,a0.w,a1.x,a1.y,a1.z,a1.w};
            float rn[8] = {b0.x,b0.y,b0.z,b0.w,b1.x,b1.y,b1.z,b1.w};
            #pragma unroll
            for (int i = 0; i < 8; i++)
                #pragma unroll
                for (int j = 0; j < 8; j++) acc[i][j] += rm[i]*rn[j];
        }
        __syncthreads();
    }

    // epilogue: e = exp(score + lts), write P, accumulate per-row partial sums
    float rowpart[8];
    #pragma unroll
    for (int i = 0; i < 8; i++) rowpart[i] = 0.f;

    #pragma unroll
    for (int i = 0; i < 8; i++) {
        int r = rb*128 + ty*8 + i;
        float* Pr = P + (size_t)head*NN + (size_t)r*1024 + cb*128 + tx*8;
        float e[8];
        #pragma unroll
        for (int j = 0; j < 8; j++) {
            e[j] = __expf(acc[i][j] + lts[tx*8 + j]);
            rowpart[i] += e[j];
        }
        *(float4*)(Pr)     = make_float4(e[0], e[1], e[2], e[3]);
        *(float4*)(Pr + 4) = make_float4(e[4], e[5], e[6], e[7]);
    }
    // reduce across tx (16-lane halves share the same ty -> same rows)
    #pragma unroll
    for (int i = 0; i < 8; i++) {
        float v = rowpart[i];
        #pragma unroll
        for (int o = 8; o > 0; o >>= 1) v += __shfl_xor_sync(0xffffffffu, v, o);
        if (tx == 0) {
            int r = rb*128 + ty*8 + i;
            g_partial[((size_t)head*SEQ + r)*8 + cb] = v;
        }
    }
}

// ---------------- 3: normalize P in place + fused hist1 ----------------
#define NH_SMEM (NBINS*4 + 128*4)
__global__ void __launch_bounds__(512) norm_hist_kernel(float* __restrict__ P) {
    extern __shared__ unsigned sh[];            // NBINS counters
    float* invs = (float*)(sh + NBINS);         // 128 row inverses
    const int head = blockIdx.y, chunk = blockIdx.x;   // chunk = 128 rows
    const int tid = threadIdx.x;
    const int lane = tid & 31;

    for (int i = tid; i < NBINS; i += 512) sh[i] = 0u;
    if (tid < 128) {
        int r = chunk*128 + tid;
        const float* pp = g_partial + ((size_t)head*SEQ + r)*8;
        float s = 0.f;
        #pragma unroll
        for (int j = 0; j < 8; j++) s += pp[j];
        invs[tid] = 1.0f / s;
    }
    __syncthreads();

    float4* base = (float4*)(P + (size_t)head*NN + (size_t)chunk*131072);
    #pragma unroll 2
    for (int it = 0; it < 64; it++) {
        int v = tid + it*512;                   // float4 index; row = v >> 8
        float4 x = base[v];
        float inv = invs[v >> 8];
        x.x *= inv; x.y *= inv; x.z *= inv; x.w *= inv;
        base[v] = x;
        float vals[4] = {x.x, x.y, x.z, x.w};
        #pragma unroll
        for (int q = 0; q < 4; q++) {
            unsigned bits = __float_as_uint(vals[q]);
            unsigned bin = bits >> 15;
            if (bin >= NBINS) bin = NBINS-1;
            unsigned mask = __match_any_sync(0xffffffffu, bin);
            if (lane == (__ffs(mask)-1)) atomicAdd(&sh[bin], (unsigned)__popc(mask));
        }
    }
    __syncthreads();
    unsigned* gh = g_hist1 + (size_t)head*NBINS;
    for (int i = tid; i < NBINS; i += 512) {
        unsigned c = sh[i];
        if (c) atomicAdd(&gh[i], c);
    }
}

// ---------------- hist2 (level-2 radix histogram) ----------------
__global__ void __launch_bounds__(256) hist2_kernel(const float* __restrict__ P) {
    extern __shared__ unsigned sh[];
    for (int i = threadIdx.x; i < NBINS; i += 256) sh[i] = 0u;
    __syncthreads();
    const int head = blockIdx.y;
    const unsigned bucket = g_bucket[head];
    const float* base = P + (size_t)head*NN + (size_t)blockIdx.x*(NN/8);
    const int lane = threadIdx.x & 31;
    for (int i = threadIdx.x; i < NN/8; i += 256) {
        unsigned bits = __float_as_uint(base[i]);
        unsigned top = bits >> 15;
        if (top >= NBINS) top = NBINS-1;
        if (top == bucket) {
            unsigned bin = bits & 0x7FFFu;
            unsigned am = __activemask();
            unsigned mask = __match_any_sync(am, bin);
            if (lane == (__ffs(mask)-1)) atomicAdd(&sh[bin], (unsigned)__popc(mask));
        }
    }
    __syncthreads();
    unsigned* gh = g_hist2 + (size_t)head*NBINS;
    for (int i = threadIdx.x; i < NBINS; i += 256) {
        unsigned c = sh[i];
        if (c) atomicAdd(&gh[i], c);
    }
}

// ---------------- select bucket / exact threshold ----------------
__global__ void __launch_bounds__(256) select1_kernel() {
    const int head = blockIdx.x, tid = threadIdx.x;
    __shared__ unsigned part[256];
    __shared__ unsigned excl[256];
    const unsigned* h = g_hist1 + (size_t)head*NBINS;
    unsigned s = 0;
    for (int j = 0; j < 128; j++) s += h[tid*128 + j];
    part[tid] = s;
    __syncthreads();
    if (tid == 0) {
        unsigned c = 0;
        for (int i = 0; i < 256; i++) { excl[i] = c; c += part[i]; }
    }
    __syncthreads();
    unsigned lo = excl[tid], hi = lo + part[tid];
    if (lo < KTH && KTH <= hi) {
        unsigned c = lo;
        for (int j = 0; j < 128; j++) {
            unsigned cnt = h[tid*128 + j];
            if (c + cnt >= KTH) { g_bucket[head] = tid*128 + j; g_rank[head] = KTH - c; break; }
            c += cnt;
        }
    }
}

__global__ void __launch_bounds__(256) select2_kernel() {
    const int head = blockIdx.x, tid = threadIdx.x;
    __shared__ unsigned part[256];
    __shared__ unsigned excl[256];
    const unsigned target = g_rank[head];
    const unsigned* h = g_hist2 + (size_t)head*NBINS;
    unsigned s = 0;
    for (int j = 0; j < 128; j++) s += h[tid*128 + j];
    part[tid] = s;
    __syncthreads();
    if (tid == 0) {
        unsigned c = 0;
        for (int i = 0; i < 256; i++) { excl[i] = c; c += part[i]; }
    }
    __syncthreads();
    unsigned lo = excl[tid], hi = lo + part[tid];
    if (lo < target && target <= hi) {
        unsigned c = lo;
        for (int j = 0; j < 128; j++) {
            unsigned cnt = h[tid*128 + j];
            if (c + cnt >= target) {
                unsigned bits = (g_bucket[head] << 15) | (unsigned)(tid*128 + j);
                g_thresh[head] = __uint_as_float(bits);
                break;
            }
            c += cnt;
        }
    }
}

// ---------------- sparsify P in place + O = P' @ V (register prefetch) ----------------
__global__ void __launch_bounds__(256) av_kernel(float* __restrict__ P) {
    __shared__ float Ps[32*132];   // [k][m] transposed, padded
    __shared__ float Vs[32*68];    // [k][d] padded
    const int head = blockIdx.y, rb = blockIdx.x;
    const int tid = threadIdx.x;
    const int tx = tid & 15, ty = tid >> 4;
    const float t = g_thresh[head];
    float* Pbase = P + (size_t)head*NN + (size_t)rb*128*1024;
    const float* Vbase = g_V + (size_t)head*SEQ*HD;

    float acc[8][4];
    #pragma unroll
    for (int i = 0; i < 8; i++)
        #pragma unroll
        for (int j = 0; j < 4; j++) acc[i][j] = 0.f;

    float4 rp[4]; float4 rv[2];
    #pragma unroll
    for (int p = 0; p < 4; p++) {
        int v = tid + p*256; int r = v >> 3, c4 = (v & 7) << 2;
        rp[p] = *(const float4*)(Pbase + (size_t)r*1024 + c4);
    }
    #pragma unroll
    for (int p = 0; p < 2; p++) {
        int v = tid + p*256; int kk = v >> 4, c4 = (v & 15) << 2;
        rv[p] = *(const float4*)(Vbase + (size_t)kk*64 + c4);
    }

    for (int kb = 0; kb < 32; kb++) {
        // sparsify, write back to P, stage into smem
        #pragma unroll
        for (int p = 0; p < 4; p++) {
            int v = tid + p*256; int r = v >> 3, c4 = (v & 7) << 2;
            float4 x = rp[p];
            x.x = (x.x < t) ? 0.f : x.x;
            x.y = (x.y < t) ? 0.f : x.y;
            x.z = (x.z < t) ? 0.f : x.z;
            x.w = (x.w < t) ? 0.f : x.w;
            *(float4*)(Pbase + (size_t)r*1024 + kb*32 + c4) = x;
            Ps[(c4+0)*132 + r] = x.x;
            Ps[(c4+1)*132 + r] = x.y;
            Ps[(c4+2)*132 + r] = x.z;
            Ps[(c4+3)*132 + r] = x.w;
        }
        #pragma unroll
        for (int p = 0; p < 2; p++) {
            int v = tid + p*256; int kk = v >> 4, c4 = (v & 15) << 2;
            *(float4*)(Vs + kk*68 + c4) = rv[p];
        }
        __syncthreads();
        if (kb + 1 < 32) {
            #pragma unroll
            for (int p = 0; p < 4; p++) {
                int v = tid + p*256; int r = v >> 3, c4 = (v & 7) << 2;
                rp[p] = *(const float4*)(Pbase + (size_t)r*1024 + (kb+1)*32 + c4);
            }
            #pragma unroll
            for (int p = 0; p < 2; p++) {
                int v = tid + p*256; int kk = v >> 4, c4 = (v & 15) << 2;
                rv[p] = *(const float4*)(Vbase + (size_t)((kb+1)*32 + kk)*64 + c4);
            }
        }
        #pragma unroll
        for (int kk = 0; kk < 32; kk++) {
            float4 m0 = *(const float4*)(Ps + kk*132 + ty*8);
            float4 m1 = *(const float4*)(Ps + kk*132 + ty*8 + 4);
            float4 n0 = *(const float4*)(Vs + kk*68 + tx*4);
            float rm[8] = {m0.x,m0.y,m0.z,m0.w,m1.x,m1.y,m1.z,m1.w};
            float rn[4] = {n0.x,n0.y,n0.z,n0.w};
            #pragma unroll
            for (int i = 0; i < 8; i++)
                #pragma unroll
                for (int j = 0; j < 4; j++) acc[i][j] += rm[i]*rn[j];
        }
        __syncthreads();
    }
    float* Obase = g_O + (size_t)head*SEQ*HD + (size_t)(rb*128 + ty*8)*64 + tx*4;
    #pragma unroll
    for (int i = 0; i < 8; i++) {
        float4 o = make_float4(acc[i][0], acc[i][1], acc[i][2], acc[i][3]);
        *(float4*)(Obase + (size_t)i*64) = o;
    }
}

// ---------------- out = O_gathered @ w_proj^T + b_proj (BK=16, prefetch) ----------------
__global__ void __launch_bounds__(256,2) proj_gemm(const float* __restrict__ W,
                                                   const float* __restrict__ bias,
                                                   float* __restrict__ out) {
    __shared__ float As[16][132];
    __shared__ float Bs[16][132];
    const int tid = threadIdx.x;
    const int bn = blockIdx.x, bm = blockIdx.y;
    const int tx = tid & 15, ty = tid >> 4;

    const float* Bptr = W + (size_t)(bn*128)*DIMC;

    float4 pa[2], pb[2];
    #pragma unroll
    for (int p = 0; p < 2; p++) {
        int f = tid + p*256; int r = f >> 2, kc = (f & 3) << 2;
        int gi = bm*128 + r;
        int b = gi >> 10, n = gi & 1023;
        int j0 = kc;
        int h = j0 >> 6, d = j0 & 63;
        pa[p] = *(const float4*)(g_O + (((size_t)b*NH + h)*SEQ + n)*HD + d);
        pb[p] = *(const float4*)(Bptr + (size_t)r*DIMC + kc);
    }

    float acc[8][8];
    #pragma unroll
    for (int i = 0; i < 8; i++)
        #pragma unroll
        for (int j = 0; j < 8; j++) acc[i][j] = 0.f;

    for (int kt = 0; kt < DIMC/16; kt++) {
        #pragma unroll
        for (int p = 0; p < 2; p++) {
            int f = tid + p*256; int r = f >> 2, kc = (f & 3) << 2;
            As[kc+0][r]=pa[p].x; As[kc+1][r]=pa[p].y; As[kc+2][r]=pa[p].z; As[kc+3][r]=pa[p].w;
            Bs[kc+0][r]=pb[p].x; Bs[kc+1][r]=pb[p].y; Bs[kc+2][r]=pb[p].z; Bs[kc+3][r]=pb[p].w;
        }
        __syncthreads();
        if (kt + 1 < DIMC/16) {
            #pragma unroll
            for (int p = 0; p < 2; p++) {
                int f = tid + p*256; int r = f >> 2, kc = (f & 3) << 2;
                int gi = bm*128 + r;
                int b = gi >> 10, n = gi & 1023;
                int j0 = (kt+1)*16 + kc;
                int h = j0 >> 6, d = j0 & 63;
                pa[p] = *(const float4*)(g_O + (((size_t)b*NH + h)*SEQ + n)*HD + d);
                pb[p] = *(const float4*)(Bptr + (size_t)r*DIMC + (kt+1)*16 + kc);
            }
        }
        #pragma unroll
        for (int kk = 0; kk < 16; kk++) {
            float4 a0 = *(const float4*)&As[kk][ty*8];
            float4 a1 = *(const float4*)&As[kk][ty*8+4];
            float4 b0 = *(const float4*)&Bs[kk][tx*8];
            float4 b1 = *(const float4*)&Bs[kk][tx*8+4];
            float rm[8] = {a0.x,a0.y,a0.z,a0.w,a1.x,a1.y,a1.z,a1.w};
            float rn[8] = {b0.x,b0.y,b0.z,b0.w,b1.x,b1.y,b1.z,b1.w};
            #pragma unroll
            for (int i = 0; i < 8; i++)
                #pragma unroll
                for (int j = 0; j < 8; j++) acc[i][j] += rm[i]*rn[j];
        }
        __syncthreads();
    }
    #pragma unroll
    for (int i = 0; i < 8; i++) {
        int oi = bm*128 + ty*8 + i;
        #pragma unroll
        for (int j = 0; j < 8; j++) {
            int oj = bn*128 + tx*8 + j;
            out[(size_t)oi*DIMC + oj] = acc[i][j] + bias[oj];
        }
    }
}

// ---------------- launch ----------------
extern "C" void kernel_launch(void* const* d_in, const int* in_sizes, int n_in,
                              void* d_out, int out_size) {
    const float* x     = (const float*)d_in[0];
    const float* ts    = (const float*)d_in[1];
    const float* wqkv  = (const float*)d_in[2];
    const float* bqkv  = (const float*)d_in[3];
    const float* wproj = (const float*)d_in[4];
    const float* bproj = (const float*)d_in[5];
    float* out = (float*)d_out;

    const size_t out_elems  = (size_t)BATCH*SEQ*DIMC;
    const size_t attn_elems = (size_t)BH*NN;
    float* P;
    if ((size_t)out_size >= out_elems + attn_elems) {
        P = out + out_elems;
    } else {
        cudaGetSymbolAddress((void**)&P, g_Pfallback);
    }

    cudaFuncSetAttribute(norm_hist_kernel, cudaFuncAttributeMaxDynamicSharedMemorySize, NH_SMEM);
    cudaFuncSetAttribute(hist2_kernel,     cudaFuncAttributeMaxDynamicSharedMemorySize, NBINS*4);

    zero_hists<<<1024, 256>>>();
    qkv_gemm<<<dim3(2304/128, 8192/128), 256>>>(x, wqkv, bqkv);
    score_gemm<<<dim3(8, 8, 96), 256>>>(ts, P);
    norm_hist_kernel<<<dim3(8, 96), 512, NH_SMEM>>>(P);
    select1_kernel<<<96, 256>>>();
    hist2_kernel<<<dim3(8, 96), 256, NBINS*4>>>(P);
    select2_kernel<<<96, 256>>>();
    av_kernel<<<dim3(8, 96), 256>>>(P);
    proj_gemm<<<dim3(768/128, 8192/128), 256>>>(wproj, bproj, out);
}

// round 4
// speedup vs baseline: 1.5461x; 1.1342x over previous
#include <cuda_runtime.h>
#include <math.h>
#include <stdint.h>

#define BATCH 8
#define SEQ   1024
#define DIMC  768
#define NH    12
#define HD    64
#define BH    (BATCH*NH)        // 96
#define NN    (SEQ*SEQ)         // 1048576
#define KTH   524288u
#define NBINS 32768
#define GCAP  131072u           // gather capacity per head
#define SAMPM 2048u             // sampled-rank margin
#define SKR   32768u            // sampled rank of KTH (KTH/16)

// ---------------- scratch (no cudaMalloc allowed) ----------------
__device__ float g_Q[(size_t)BH*SEQ*HD];
__device__ float g_K[(size_t)BH*SEQ*HD];
__device__ float g_V[(size_t)BH*SEQ*HD];
__device__ float g_O[(size_t)BH*SEQ*HD];
__device__ float g_partial[(size_t)BH*SEQ*8];
__device__ float g_inv[(size_t)BH*SEQ];
__device__ float g_Pfallback[(size_t)BH*NN];
__device__ float g_gath[(size_t)BH*GCAP];
__device__ unsigned g_samphist[(size_t)BH*NBINS];
__device__ unsigned g_hist1[(size_t)BH*NBINS];   // fallback only
__device__ unsigned g_hist2[(size_t)BH*NBINS];   // fallback only
__device__ unsigned g_gcnt[BH];
__device__ unsigned g_cntbelow[BH];
__device__ unsigned g_wlo[BH];
__device__ unsigned g_whi[BH];
__device__ unsigned g_ok[BH];
__device__ unsigned g_bucket[BH];
__device__ unsigned g_rank[BH];
__device__ float    g_thresh[BH];

// ---------------- 0: zero counters/hists ----------------
__global__ void zero_small() {
    size_t n = (size_t)BH*NBINS;
    for (size_t i = blockIdx.x*(size_t)blockDim.x + threadIdx.x; i < n; i += (size_t)gridDim.x*blockDim.x) {
        g_samphist[i] = 0u; g_hist1[i] = 0u; g_hist2[i] = 0u;
    }
    if (blockIdx.x == 0 && threadIdx.x < BH) {
        g_gcnt[threadIdx.x] = 0u;
        g_cntbelow[threadIdx.x] = 0u;
        g_ok[threadIdx.x] = 0u;
    }
}

// ---------------- 1: QKV GEMM (BK=16, register-prefetch double buffer) ----------------
__global__ void __launch_bounds__(256,2) qkv_gemm(const float* __restrict__ X,
                                                  const float* __restrict__ W,
                                                  const float* __restrict__ bias) {
    __shared__ float As[16][132];
    __shared__ float Bs[16][132];
    const int tid = threadIdx.x;
    const int bn = blockIdx.x, bm = blockIdx.y;
    const int tx = tid & 15, ty = tid >> 4;

    const float* Aptr = X + (size_t)(bm*128)*DIMC;
    const float* Bptr = W + (size_t)(bn*128)*DIMC;

    float4 pa[2], pb[2];
    #pragma unroll
    for (int p = 0; p < 2; p++) {
        int f = tid + p*256; int r = f >> 2, kc = (f & 3) << 2;
        pa[p] = *(const float4*)(Aptr + (size_t)r*DIMC + kc);
        pb[p] = *(const float4*)(Bptr + (size_t)r*DIMC + kc);
    }

    float acc[8][8];
    #pragma unroll
    for (int i = 0; i < 8; i++)
        #pragma unroll
        for (int j = 0; j < 8; j++) acc[i][j] = 0.f;

    for (int kt = 0; kt < DIMC/16; kt++) {
        #pragma unroll
        for (int p = 0; p < 2; p++) {
            int f = tid + p*256; int r = f >> 2, kc = (f & 3) << 2;
            As[kc+0][r]=pa[p].x; As[kc+1][r]=pa[p].y; As[kc+2][r]=pa[p].z; As[kc+3][r]=pa[p].w;
            Bs[kc+0][r]=pb[p].x; Bs[kc+1][r]=pb[p].y; Bs[kc+2][r]=pb[p].z; Bs[kc+3][r]=pb[p].w;
        }
        __syncthreads();
        if (kt + 1 < DIMC/16) {
            #pragma unroll
            for (int p = 0; p < 2; p++) {
                int f = tid + p*256; int r = f >> 2, kc = (f & 3) << 2;
                pa[p] = *(const float4*)(Aptr + (size_t)r*DIMC + (kt+1)*16 + kc);
                pb[p] = *(const float4*)(Bptr + (size_t)r*DIMC + (kt+1)*16 + kc);
            }
        }
        #pragma unroll
        for (int kk = 0; kk < 16; kk++) {
            float4 a0 = *(const float4*)&As[kk][ty*8];
            float4 a1 = *(const float4*)&As[kk][ty*8+4];
            float4 b0 = *(const float4*)&Bs[kk][tx*8];
            float4 b1 = *(const float4*)&Bs[kk][tx*8+4];
            float rm[8] = {a0.x,a0.y,a0.z,a0.w,a1.x,a1.y,a1.z,a1.w};
            float rn[8] = {b0.x,b0.y,b0.z,b0.w,b1.x,b1.y,b1.z,b1.w};
            #pragma unroll
            for (int i = 0; i < 8; i++)
                #pragma unroll
                for (int j = 0; j < 8; j++) acc[i][j] += rm[i]*rn[j];
        }
        __syncthreads();
    }
    #pragma unroll
    for (int i = 0; i < 8; i++) {
        int gi = bm*128 + ty*8 + i;
        int b = gi >> 10, n = gi & 1023;
        #pragma unroll
        for (int j = 0; j < 8; j++) {
            int gj = bn*128 + tx*8 + j;
            float val = acc[i][j] + bias[gj];
            int t = gj / DIMC;
            int r = gj - t*DIMC;
            int h = r >> 6, d = r & 63;
            size_t dst = (((size_t)b*NH + h)*SEQ + n)*HD + d;
            if (t == 0)      g_Q[dst] = val * 0.125f;
            else if (t == 1) g_K[dst] = val;
            else             g_V[dst] = val;
        }
    }
}

// ---------------- 2: score GEMM + exp (unnormalized softmax numerator) ----------------
__global__ void __launch_bounds__(256,2) score_gemm(const float* __restrict__ ts,
                                                    float* __restrict__ P) {
    __shared__ float Asr[16][132];
    __shared__ float Bs[16][132];
    __shared__ float lts[128];

    const int head = blockIdx.z;
    const int b = head / NH;
    const int rb = blockIdx.y, cb = blockIdx.x;
    const int tid = threadIdx.x;
    const int tx = tid & 15, ty = tid >> 4;

    const float* Aptr = g_Q + (size_t)head*SEQ*HD + (size_t)(rb*128)*HD;
    const float* Bptr = g_K + (size_t)head*SEQ*HD + (size_t)(cb*128)*HD;

    if (tid < 128) lts[tid] = logf(ts[b*SEQ + cb*128 + tid]);

    float4 pa[2], pb[2];
    #pragma unroll
    for (int p = 0; p < 2; p++) {
        int f = tid + p*256; int r = f >> 2, kc = (f & 3) << 2;
        pa[p] = *(const float4*)(Aptr + (size_t)r*HD + kc);
        pb[p] = *(const float4*)(Bptr + (size_t)r*HD + kc);
    }

    float acc[8][8];
    #pragma unroll
    for (int i = 0; i < 8; i++)
        #pragma unroll
        for (int j = 0; j < 8; j++) acc[i][j] = 0.f;

    for (int kt = 0; kt < HD/16; kt++) {
        #pragma unroll
        for (int p = 0; p < 2; p++) {
            int f = tid + p*256; int r = f >> 2, kc = (f & 3) << 2;
            Asr[kc+0][r]=pa[p].x; Asr[kc+1][r]=pa[p].y; Asr[kc+2][r]=pa[p].z; Asr[kc+3][r]=pa[p].w;
            Bs[kc+0][r]=pb[p].x;  Bs[kc+1][r]=pb[p].y;  Bs[kc+2][r]=pb[p].z;  Bs[kc+3][r]=pb[p].w;
        }
        __syncthreads();
        if (kt + 1 < HD/16) {
            #pragma unroll
            for (int p = 0; p < 2; p++) {
                int f = tid + p*256; int r = f >> 2, kc = (f & 3) << 2;
                pa[p] = *(const float4*)(Aptr + (size_t)r*HD + (kt+1)*16 + kc);
                pb[p] = *(const float4*)(Bptr + (size_t)r*HD + (kt+1)*16 + kc);
            }
        }
        #pragma unroll
        for (int kk = 0; kk < 16; kk++) {
            float4 a0 = *(const float4*)&Asr[kk][ty*8];
            float4 a1 = *(const float4*)&Asr[kk][ty*8+4];
            float4 b0 = *(const float4*)&Bs[kk][tx*8];
            float4 b1 = *(const float4*)&Bs[kk][tx*8+4];
            float rm[8] = {a0.x,a0.y,a0.z,a0.w,a1.x,a1.y,a1.z,a1.w};
            float rn[8] = {b0.x,b0.y,b0.z,b0.w,b1.x,b1.y,b1.z,b1.w};
            #pragma unroll
            for (int i = 0; i < 8; i++)
                #pragma unroll
                for (int j = 0; j < 8; j++) acc[i][j] += rm[i]*rn[j];
        }
        __syncthreads();
    }

    float rowpart[8];
    #pragma unroll
    for (int i = 0; i < 8; i++) rowpart[i] = 0.f;

    #pragma unroll
    for (int i = 0; i < 8; i++) {
        int r = rb*128 + ty*8 + i;
        float* Pr = P + (size_t)head*NN + (size_t)r*1024 + cb*128 + tx*8;
        float e[8];
        #pragma unroll
        for (int j = 0; j < 8; j++) {
            e[j] = __expf(acc[i][j] + lts[tx*8 + j]);
            rowpart[i] += e[j];
        }
        *(float4*)(Pr)     = make_float4(e[0], e[1], e[2], e[3]);
        *(float4*)(Pr + 4) = make_float4(e[4], e[5], e[6], e[7]);
    }
    #pragma unroll
    for (int i = 0; i < 8; i++) {
        float v = rowpart[i];
        #pragma unroll
        for (int o = 8; o > 0; o >>= 1) v += __shfl_xor_sync(0xffffffffu, v, o);
        if (tx == 0) {
            int r = rb*128 + ty*8 + i;
            g_partial[((size_t)head*SEQ + r)*8 + cb] = v;
        }
    }
}

// ---------------- 3: row inverse sums ----------------
__global__ void __launch_bounds__(1024) rowinv_kernel() {
    const int head = blockIdx.x;
    const int r = threadIdx.x;
    const float* pp = g_partial + ((size_t)head*SEQ + r)*8;
    float s = 0.f;
    #pragma unroll
    for (int j = 0; j < 8; j++) s += pp[j];
    g_inv[(size_t)head*SEQ + r] = 1.0f / s;
}

// ---------------- 4: sampled histogram (1/16 of float4s) ----------------
__global__ void __launch_bounds__(256) sample_hist(const float* __restrict__ P) {
    extern __shared__ unsigned sh[];
    const int head = blockIdx.y, q = blockIdx.x;   // q in [0,4)
    const int tid = threadIdx.x, lane = tid & 31;
    for (int i = tid; i < NBINS; i += 256) sh[i] = 0u;
    __syncthreads();
    const float4* base = (const float4*)(P + (size_t)head*NN);
    const float* invh = g_inv + (size_t)head*SEQ;
    // per CTA: 4096 sampled float4 (indices q*65536 + i*16)
    for (int it = 0; it < 16; it++) {
        int i = tid + it*256;
        int v = q*65536 + i*16;
        float4 x = base[v];
        float inv = invh[v >> 8];
        float pv[4] = {x.x*inv, x.y*inv, x.z*inv, x.w*inv};
        #pragma unroll
        for (int e = 0; e < 4; e++) {
            unsigned bin = __float_as_uint(pv[e]) >> 15;
            if (bin >= NBINS) bin = NBINS-1;
            unsigned mask = __match_any_sync(0xffffffffu, bin);
            if (lane == (__ffs(mask)-1)) atomicAdd(&sh[bin], (unsigned)__popc(mask));
        }
    }
    __syncthreads();
    unsigned* gh = g_samphist + (size_t)head*NBINS;
    for (int i = tid; i < NBINS; i += 256) {
        unsigned c = sh[i];
        if (c) atomicAdd(&gh[i], c);
    }
}

// ---------------- 5: window selection from sampled histogram ----------------
__global__ void __launch_bounds__(256) window_select() {
    const int head = blockIdx.x, tid = threadIdx.x;
    __shared__ unsigned part[256];
    __shared__ unsigned excl[256];
    const unsigned* h = g_samphist + (size_t)head*NBINS;
    unsigned s = 0;
    for (int j = 0; j < 128; j++) s += h[tid*128 + j];
    part[tid] = s;
    __syncthreads();
    if (tid == 0) {
        unsigned c = 0;
        for (int i = 0; i < 256; i++) { excl[i] = c; c += part[i]; }
    }
    __syncthreads();
    unsigned S = excl[255] + part[255];
    unsigned T1 = (SKR > SAMPM) ? (SKR - SAMPM) : 1u;
    unsigned T2 = (SKR + SAMPM < S) ? (SKR + SAMPM) : S;
    unsigned lo = excl[tid], hi = lo + part[tid];
    if (lo < T1 && T1 <= hi) {
        unsigned c = lo;
        for (int j = 0; j < 128; j++) {
            c += h[tid*128 + j];
            if (c >= T1) { g_wlo[head] = tid*128 + j; break; }
        }
    }
    if (lo < T2 && T2 <= hi) {
        unsigned c = lo;
        for (int j = 0; j < 128; j++) {
            c += h[tid*128 + j];
            if (c >= T2) { g_whi[head] = tid*128 + j; break; }
        }
    }
}

// ---------------- 6: exact count-below + gather window elements ----------------
__global__ void __launch_bounds__(512) count_gather(const float* __restrict__ P) {
    __shared__ float sinv[128];
    __shared__ unsigned s_below;
    const int head = blockIdx.y, chunk = blockIdx.x;
    const int tid = threadIdx.x, lane = tid & 31;
    if (tid == 0) s_below = 0;
    if (tid < 128) sinv[tid] = g_inv[(size_t)head*SEQ + chunk*128 + tid];
    __syncthreads();
    const unsigned wlo = g_wlo[head], whi = g_whi[head];
    const float4* base = (const float4*)(P + (size_t)head*NN + (size_t)chunk*131072);
    float* gout = g_gath + (size_t)head*GCAP;
    unsigned below = 0;
    for (int it = 0; it < 64; it++) {
        int v = tid + it*512;
        float4 x = base[v];
        float inv = sinv[v >> 8];
        float pv[4] = {x.x*inv, x.y*inv, x.z*inv, x.w*inv};
        #pragma unroll
        for (int e = 0; e < 4; e++) {
            unsigned bits = __float_as_uint(pv[e]);
            unsigned bin = bits >> 15;
            below += (bin < wlo) ? 1u : 0u;
            bool inw = (bin >= wlo) && (bin <= whi);
            unsigned bal = __ballot_sync(0xffffffffu, inw);
            if (bal) {
                unsigned cnt = __popc(bal);
                unsigned basep = 0;
                if (lane == 0) basep = atomicAdd(&g_gcnt[head], cnt);
                basep = __shfl_sync(0xffffffffu, basep, 0);
                if (inw) {
                    unsigned pos = basep + __popc(bal & ((1u << lane) - 1u));
                    if (pos < GCAP) gout[pos] = pv[e];
                }
            }
        }
    }
    #pragma unroll
    for (int o = 16; o > 0; o >>= 1) below += __shfl_xor_sync(0xffffffffu, below, o);
    if (lane == 0) atomicAdd(&s_below, below);
    __syncthreads();
    if (tid == 0) atomicAdd(&g_cntbelow[head], s_below);
}

// ---------------- 7: verify window ----------------
__global__ void check_ok() {
    int t = threadIdx.x;
    if (t < BH) {
        unsigned cb = g_cntbelow[t];
        unsigned gc = g_gcnt[t];
        bool ok = (gc <= GCAP) && (cb < KTH) && (KTH <= cb + gc);
        g_ok[t] = ok ? 1u : 0u;
    }
}

// ---------------- fallback: full exact histograms (early-exit when ok) ----------------
__global__ void __launch_bounds__(512) fb_hist1(const float* __restrict__ P) {
    const int head = blockIdx.y;
    if (g_ok[head]) return;
    extern __shared__ unsigned sh[];
    __shared__ float sinv[128];
    const int chunk = blockIdx.x;
    const int tid = threadIdx.x, lane = tid & 31;
    for (int i = tid; i < NBINS; i += 512) sh[i] = 0u;
    if (tid < 128) sinv[tid] = g_inv[(size_t)head*SEQ + chunk*128 + tid];
    __syncthreads();
    const float4* base = (const float4*)(P + (size_t)head*NN + (size_t)chunk*131072);
    for (int it = 0; it < 64; it++) {
        int v = tid + it*512;
        float4 x = base[v];
        float inv = sinv[v >> 8];
        float pv[4] = {x.x*inv, x.y*inv, x.z*inv, x.w*inv};
        #pragma unroll
        for (int e = 0; e < 4; e++) {
            unsigned bin = __float_as_uint(pv[e]) >> 15;
            if (bin >= NBINS) bin = NBINS-1;
            unsigned mask = __match_any_sync(0xffffffffu, bin);
            if (lane == (__ffs(mask)-1)) atomicAdd(&sh[bin], (unsigned)__popc(mask));
        }
    }
    __syncthreads();
    unsigned* gh = g_hist1 + (size_t)head*NBINS;
    for (int i = tid; i < NBINS; i += 512) {
        unsigned c = sh[i];
        if (c) atomicAdd(&gh[i], c);
    }
}

__global__ void __launch_bounds__(256) fb_select1() {
    const int head = blockIdx.x, tid = threadIdx.x;
    if (g_ok[head]) return;
    __shared__ unsigned part[256];
    __shared__ unsigned excl[256];
    const unsigned* h = g_hist1 + (size_t)head*NBINS;
    unsigned s = 0;
    for (int j = 0; j < 128; j++) s += h[tid*128 + j];
    part[tid] = s;
    __syncthreads();
    if (tid == 0) {
        unsigned c = 0;
        for (int i = 0; i < 256; i++) { excl[i] = c; c += part[i]; }
    }
    __syncthreads();
    unsigned lo = excl[tid], hi = lo + part[tid];
    if (lo < KTH && KTH <= hi) {
        unsigned c = lo;
        for (int j = 0; j < 128; j++) {
            unsigned cnt = h[tid*128 + j];
            if (c + cnt >= KTH) { g_bucket[head] = tid*128 + j; g_rank[head] = KTH - c; break; }
            c += cnt;
        }
    }
}

__global__ void __launch_bounds__(512) fb_hist2(const float* __restrict__ P) {
    const int head = blockIdx.y;
    if (g_ok[head]) return;
    extern __shared__ unsigned sh[];
    __shared__ float sinv[128];
    const int chunk = blockIdx.x;
    const int tid = threadIdx.x, lane = tid & 31;
    for (int i = tid; i < NBINS; i += 512) sh[i] = 0u;
    if (tid < 128) sinv[tid] = g_inv[(size_t)head*SEQ + chunk*128 + tid];
    __syncthreads();
    const unsigned bucket = g_bucket[head];
    const float4* base = (const float4*)(P + (size_t)head*NN + (size_t)chunk*131072);
    for (int it = 0; it < 64; it++) {
        int v = tid + it*512;
        float4 x = base[v];
        float inv = sinv[v >> 8];
        float pv[4] = {x.x*inv, x.y*inv, x.z*inv, x.w*inv};
        #pragma unroll
        for (int e = 0; e < 4; e++) {
            unsigned bits = __float_as_uint(pv[e]);
            unsigned top = bits >> 15;
            bool inb = (top == bucket);
            unsigned bin = inb ? (bits & 0x7FFFu) : 0xFFFFFFFFu;
            unsigned mask = __match_any_sync(0xffffffffu, bin);
            if (inb && lane == (__ffs(mask)-1)) atomicAdd(&sh[bin], (unsigned)__popc(mask));
        }
    }
    __syncthreads();
    unsigned* gh = g_hist2 + (size_t)head*NBINS;
    for (int i = tid; i < NBINS; i += 512) {
        unsigned c = sh[i];
        if (c) atomicAdd(&gh[i], c);
    }
}

__global__ void __launch_bounds__(256) fb_select2() {
    const int head = blockIdx.x, tid = threadIdx.x;
    if (g_ok[head]) return;
    __shared__ unsigned part[256];
    __shared__ unsigned excl[256];
    const unsigned target = g_rank[head];
    const unsigned* h = g_hist2 + (size_t)head*NBINS;
    unsigned s = 0;
    for (int j = 0; j < 128; j++) s += h[tid*128 + j];
    part[tid] = s;
    __syncthreads();
    if (tid == 0) {
        unsigned c = 0;
        for (int i = 0; i < 256; i++) { excl[i] = c; c += part[i]; }
    }
    __syncthreads();
    unsigned lo = excl[tid], hi = lo + part[tid];
    if (lo < target && target <= hi) {
        unsigned c = lo;
        for (int j = 0; j < 128; j++) {
            unsigned cnt = h[tid*128 + j];
            if (c + cnt >= target) {
                unsigned bits = (g_bucket[head] << 15) | (unsigned)(tid*128 + j);
                g_thresh[head] = __uint_as_float(bits);
                break;
            }
            c += cnt;
        }
    }
}

// ---------------- 8: exact 2-level select over gathered values ----------------
__global__ void __launch_bounds__(1024) final_select() {
    const int head = blockIdx.x;
    if (!g_ok[head]) return;
    extern __shared__ unsigned hist[];
    __shared__ unsigned part[1024];
    __shared__ unsigned excl[1024];
    __shared__ unsigned s_bucket, s_t2;
    const int tid = threadIdx.x, lane = tid & 31;
    const unsigned n = g_gcnt[head];
    const unsigned target = KTH - g_cntbelow[head];
    const float* g = g_gath + (size_t)head*GCAP;
    const unsigned ntrip = (n + 1023u) & ~1023u;

    for (int i = tid; i < NBINS; i += 1024) hist[i] = 0u;
    __syncthreads();
    for (unsigned i = tid; i < ntrip; i += 1024) {
        bool valid = (i < n);
        unsigned bin = valid ? (__float_as_uint(g[i]) >> 15) : 0xFFFFFFFFu;
        unsigned mask = __match_any_sync(0xffffffffu, bin);
        if (valid && lane == (__ffs(mask)-1)) atomicAdd(&hist[bin], (unsigned)__popc(mask));
    }
    __syncthreads();
    {
        unsigned s = 0;
        for (int j = 0; j < 32; j++) s += hist[tid*32 + j];
        part[tid] = s;
        __syncthreads();
        if (tid == 0) {
            unsigned c = 0;
            for (int i = 0; i < 1024; i++) { excl[i] = c; c += part[i]; }
        }
        __syncthreads();
        unsigned lo = excl[tid], hi = lo + part[tid];
        if (lo < target && target <= hi) {
            unsigned c = lo;
            for (int j = 0; j < 32; j++) {
                unsigned cnt = hist[tid*32 + j];
                if (c + cnt >= target) { s_bucket = tid*32 + j; s_t2 = target - c; break; }
                c += cnt;
            }
        }
    }
    __syncthreads();
    const unsigned bucket = s_bucket;
    const unsigned t2 = s_t2;
    __syncthreads();
    for (int i = tid; i < NBINS; i += 1024) hist[i] = 0u;
    __syncthreads();
    for (unsigned i = tid; i < ntrip; i += 1024) {
        bool valid = (i < n);
        unsigned bits = valid ? __float_as_uint(g[i]) : 0xFFFFFFFFu;
        bool inb = valid && ((bits >> 15) == bucket);
        unsigned bin = inb ? (bits & 0x7FFFu) : 0xFFFFFFFFu;
        unsigned mask = __match_any_sync(0xffffffffu, bin);
        if (inb && lane == (__ffs(mask)-1)) atomicAdd(&hist[bin], (unsigned)__popc(mask));
    }
    __syncthreads();
    {
        unsigned s = 0;
        for (int j = 0; j < 32; j++) s += hist[tid*32 + j];
        part[tid] = s;
        __syncthreads();
        if (tid == 0) {
            unsigned c = 0;
            for (int i = 0; i < 1024; i++) { excl[i] = c; c += part[i]; }
        }
        __syncthreads();
        unsigned lo = excl[tid], hi = lo + part[tid];
        if (lo < t2 && t2 <= hi) {
            unsigned c = lo;
            for (int j = 0; j < 32; j++) {
                unsigned cnt = hist[tid*32 + j];
                if (c + cnt >= t2) {
                    unsigned bits = (bucket << 15) | (unsigned)(tid*32 + j);
                    g_thresh[head] = __uint_as_float(bits);
                    break;
                }
                c += cnt;
            }
        }
    }
}

// ---------------- 9: normalize + sparsify P + O = P' @ V ----------------
__global__ void __launch_bounds__(256) av_kernel(float* __restrict__ P) {
    __shared__ float Ps[32*132];
    __shared__ float Vs[32*68];
    __shared__ float sinv[128];
    const int head = blockIdx.y, rb = blockIdx.x;
    const int tid = threadIdx.x;
    const int tx = tid & 15, ty = tid >> 4;
    const float t = g_thresh[head];
    float* Pbase = P + (size_t)head*NN + (size_t)rb*128*1024;
    const float* Vbase = g_V + (size_t)head*SEQ*HD;

    if (tid < 128) sinv[tid] = g_inv[(size_t)head*SEQ + rb*128 + tid];

    float acc[8][4];
    #pragma unroll
    for (int i = 0; i < 8; i++)
        #pragma unroll
        for (int j = 0; j < 4; j++) acc[i][j] = 0.f;

    float4 rp[4]; float4 rv[2];
    #pragma unroll
    for (int p = 0; p < 4; p++) {
        int v = tid + p*256; int r = v >> 3, c4 = (v & 7) << 2;
        rp[p] = *(const float4*)(Pbase + (size_t)r*1024 + c4);
    }
    #pragma unroll
    for (int p = 0; p < 2; p++) {
        int v = tid + p*256; int kk = v >> 4, c4 = (v & 15) << 2;
        rv[p] = *(const float4*)(Vbase + (size_t)kk*64 + c4);
    }
    __syncthreads();

    for (int kb = 0; kb < 32; kb++) {
        #pragma unroll
        for (int p = 0; p < 4; p++) {
            int v = tid + p*256; int r = v >> 3, c4 = (v & 7) << 2;
            float inv = sinv[r];
            float4 x = rp[p];
            x.x *= inv; x.y *= inv; x.z *= inv; x.w *= inv;
            x.x = (x.x < t) ? 0.f : x.x;
            x.y = (x.y < t) ? 0.f : x.y;
            x.z = (x.z < t) ? 0.f : x.z;
            x.w = (x.w < t) ? 0.f : x.w;
            *(float4*)(Pbase + (size_t)r*1024 + kb*32 + c4) = x;
            Ps[(c4+0)*132 + r] = x.x;
            Ps[(c4+1)*132 + r] = x.y;
            Ps[(c4+2)*132 + r] = x.z;
            Ps[(c4+3)*132 + r] = x.w;
        }
        #pragma unroll
        for (int p = 0; p < 2; p++) {
            int v = tid + p*256; int kk = v >> 4, c4 = (v & 15) << 2;
            *(float4*)(Vs + kk*68 + c4) = rv[p];
        }
        __syncthreads();
        if (kb + 1 < 32) {
            #pragma unroll
            for (int p = 0; p < 4; p++) {
                int v = tid + p*256; int r = v >> 3, c4 = (v & 7) << 2;
                rp[p] = *(const float4*)(Pbase + (size_t)r*1024 + (kb+1)*32 + c4);
            }
            #pragma unroll
            for (int p = 0; p < 2; p++) {
                int v = tid + p*256; int kk = v >> 4, c4 = (v & 15) << 2;
                rv[p] = *(const float4*)(Vbase + (size_t)((kb+1)*32 + kk)*64 + c4);
            }
        }
        #pragma unroll
        for (int kk = 0; kk < 32; kk++) {
            float4 m0 = *(const float4*)(Ps + kk*132 + ty*8);
            float4 m1 = *(const float4*)(Ps + kk*132 + ty*8 + 4);
            float4 n0 = *(const float4*)(Vs + kk*68 + tx*4);
            float rm[8] = {m0.x,m0.y,m0.z,m0.w,m1.x,m1.y,m1.z,m1.w};
            float rn[4] = {n0.x,n0.y,n0.z,n0.w};
            #pragma unroll
            for (int i = 0; i < 8; i++)
                #pragma unroll
                for (int j = 0; j < 4; j++) acc[i][j] += rm[i]*rn[j];
        }
        __syncthreads();
    }
    float* Obase = g_O + (size_t)head*SEQ*HD + (size_t)(rb*128 + ty*8)*64 + tx*4;
    #pragma unroll
    for (int i = 0; i < 8; i++) {
        float4 o = make_float4(acc[i][0], acc[i][1], acc[i][2], acc[i][3]);
        *(float4*)(Obase + (size_t)i*64) = o;
    }
}

// ---------------- 10: out = O_gathered @ w_proj^T + b_proj ----------------
__global__ void __launch_bounds__(256,2) proj_gemm(const float* __restrict__ W,
                                                   const float* __restrict__ bias,
                                                   float* __restrict__ out) {
    __shared__ float As[16][132];
    __shared__ float Bs[16][132];
    const int tid = threadIdx.x;
    const int bn = blockIdx.x, bm = blockIdx.y;
    const int tx = tid & 15, ty = tid >> 4;

    const float* Bptr = W + (size_t)(bn*128)*DIMC;

    float4 pa[2], pb[2];
    #pragma unroll
    for (int p = 0; p < 2; p++) {
        int f = tid + p*256; int r = f >> 2, kc = (f & 3) << 2;
        int gi = bm*128 + r;
        int b = gi >> 10, n = gi & 1023;
        int h = kc >> 6, d = kc & 63;
        pa[p] = *(const float4*)(g_O + (((size_t)b*NH + h)*SEQ + n)*HD + d);
        pb[p] = *(const float4*)(Bptr + (size_t)r*DIMC + kc);
    }

    float acc[8][8];
    #pragma unroll
    for (int i = 0; i < 8; i++)
        #pragma unroll
        for (int j = 0; j < 8; j++) acc[i][j] = 0.f;

    for (int kt = 0; kt < DIMC/16; kt++) {
        #pragma unroll
        for (int p = 0; p < 2; p++) {
            int f = tid + p*256; int r = f >> 2, kc = (f & 3) << 2;
            As[kc+0][r]=pa[p].x; As[kc+1][r]=pa[p].y; As[kc+2][r]=pa[p].z; As[kc+3][r]=pa[p].w;
            Bs[kc+0][r]=pb[p].x; Bs[kc+1][r]=pb[p].y; Bs[kc+2][r]=pb[p].z; Bs[kc+3][r]=pb[p].w;
        }
        __syncthreads();
        if (kt + 1 < DIMC/16) {
            #pragma unroll
            for (int p = 0; p < 2; p++) {
                int f = tid + p*256; int r = f >> 2, kc = (f & 3) << 2;
                int gi = bm*128 + r;
                int b = gi >> 10, n = gi & 1023;
                int j0 = (kt+1)*16 + kc;
                int h = j0 >> 6, d = j0 & 63;
                pa[p] = *(const float4*)(g_O + (((size_t)b*NH + h)*SEQ + n)*HD + d);
                pb[p] = *(const float4*)(Bptr + (size_t)r*DIMC + (kt+1)*16 + kc);
            }
        }
        #pragma unroll
        for (int kk = 0; kk < 16; kk++) {
            float4 a0 = *(const float4*)&As[kk][ty*8];
            float4 a1 = *(const float4*)&As[kk][ty*8+4];
            float4 b0 = *(const float4*)&Bs[kk][tx*8];
            float4 b1 = *(const float4*)&Bs[kk][tx*8+4];
            float rm[8] = {a0.x,a0.y,a0.z,a0.w,a1.x,a1.y,a1.z,a1.w};
            float rn[8] = {b0.x,b0.y,b0.z,b0.w,b1.x,b1.y,b1.z,b1.w};
            #pragma unroll
            for (int i = 0; i < 8; i++)
                #pragma unroll
                for (int j = 0; j < 8; j++) acc[i][j] += rm[i]*rn[j];
        }
        __syncthreads();
    }
    #pragma unroll
    for (int i = 0; i < 8; i++) {
        int oi = bm*128 + ty*8 + i;
        #pragma unroll
        for (int j = 0; j < 8; j++) {
            int oj = bn*128 + tx*8 + j;
            out[(size_t)oi*DIMC + oj] = acc[i][j] + bias[oj];
        }
    }
}

// ---------------- launch ----------------
extern "C" void kernel_launch(void* const* d_in, const int* in_sizes, int n_in,
                              void* d_out, int out_size) {
    const float* x     = (const float*)d_in[0];
    const float* ts    = (const float*)d_in[1];
    const float* wqkv  = (const float*)d_in[2];
    const float* bqkv  = (const float*)d_in[3];
    const float* wproj = (const float*)d_in[4];
    const float* bproj = (const float*)d_in[5];
    float* out = (float*)d_out;

    const size_t out_elems  = (size_t)BATCH*SEQ*DIMC;
    const size_t attn_elems = (size_t)BH*NN;
    float* P;
    if ((size_t)out_size >= out_elems + attn_elems) {
        P = out + out_elems;
    } else {
        cudaGetSymbolAddress((void**)&P, g_Pfallback);
    }

    cudaFuncSetAttribute(sample_hist,  cudaFuncAttributeMaxDynamicSharedMemorySize, NBINS*4);
    cudaFuncSetAttribute(fb_hist1,     cudaFuncAttributeMaxDynamicSharedMemorySize, NBINS*4);
    cudaFuncSetAttribute(fb_hist2,     cudaFuncAttributeMaxDynamicSharedMemorySize, NBINS*4);
    cudaFuncSetAttribute(final_select, cudaFuncAttributeMaxDynamicSharedMemorySize, NBINS*4);

    zero_small<<<1024, 256>>>();
    qkv_gemm<<<dim3(2304/128, 8192/128), 256>>>(x, wqkv, bqkv);
    score_gemm<<<dim3(8, 8, 96), 256>>>(ts, P);
    rowinv_kernel<<<96, 1024>>>();
    sample_hist<<<dim3(4, 96), 256, NBINS*4>>>(P);
    window_select<<<96, 256>>>();
    count_gather<<<dim3(8, 96), 512>>>(P);
    check_ok<<<1, 128>>>();
    fb_hist1<<<dim3(8, 96), 512, NBINS*4>>>(P);
    fb_select1<<<96, 256>>>();
    fb_hist2<<<dim3(8, 96), 512, NBINS*4>>>(P);
    fb_select2<<<96, 256>>>();
    final_select<<<96, 1024, NBINS*4>>>();
    av_kernel<<<dim3(8, 96), 256>>>(P);
    proj_gemm<<<dim3(768/128, 8192/128), 256>>>(wproj, bproj, out);
}

// round 6
// speedup vs baseline: 1.5611x; 1.0097x over previous
#include <cuda_runtime.h>
#include <math.h>
#include <stdint.h>

#define BATCH 8
#define SEQ   1024
#define DIMC  768
#define NH    12
#define HD    64
#define BH    (BATCH*NH)        // 96
#define NN    (SEQ*SEQ)         // 1048576
#define KTH   524288u
#define NBINS 32768
#define GCAP  131072u
#define SAMPM 2048u
#define SKR   32768u

// ---------------- scratch ----------------
__device__ float g_Q[(size_t)BH*SEQ*HD];
__device__ float g_K[(size_t)BH*SEQ*HD];
__device__ float g_V[(size_t)BH*SEQ*HD];
__device__ float g_O[(size_t)BH*SEQ*HD];
__device__ float g_partial[(size_t)BH*SEQ*8];
__device__ float g_inv[(size_t)BH*SEQ];
__device__ float g_Pfallback[(size_t)BH*NN];
__device__ float g_gath[(size_t)BH*GCAP];
__device__ unsigned g_samphist[(size_t)BH*NBINS];
__device__ unsigned g_hist1[(size_t)BH*NBINS];
__device__ unsigned g_hist2[(size_t)BH*NBINS];
__device__ unsigned g_gcnt[BH];
__device__ unsigned g_cntbelow[BH];
__device__ unsigned g_wlo[BH];
__device__ unsigned g_whi[BH];
__device__ unsigned g_ok[BH];
__device__ unsigned g_bucket[BH];
__device__ unsigned g_rank[BH];
__device__ float    g_thresh[BH];

// ================= tf32 mma helpers (sm_80+, works on plain sm_100 target) =========
__device__ __forceinline__ void split_tf32(float v, uint32_t& hi, uint32_t& lo) {
    asm("cvt.rna.tf32.f32 %0, %1;" : "=r"(hi) : "f"(v));
    float r = v - __uint_as_float(hi);
    asm("cvt.rna.tf32.f32 %0, %1;" : "=r"(lo) : "f"(r));
}
#define MMA_TF32(c, a, b0, b1) \
    asm volatile("mma.sync.aligned.m16n8k8.row.col.f32.tf32.tf32.f32 " \
        "{%0,%1,%2,%3}, {%4,%5,%6,%7}, {%8,%9}, {%0,%1,%2,%3};" \
        : "+f"((c)[0]), "+f"((c)[1]), "+f"((c)[2]), "+f"((c)[3]) \
        : "r"((a)[0]), "r"((a)[1]), "r"((a)[2]), "r"((a)[3]), "r"(b0), "r"(b1))

// ---------------- tensor-core GEMM via 3xTF32: C = A[128m,K] @ W[128n,K]^T ----------
// mode 0: A = X (K=768), epilogue scatters to Q/K/V (+bias, Q*0.125)
// mode 1: A = g_O gathered (K=768), epilogue writes out (+bias)
__global__ void __launch_bounds__(256) mma_gemm(int mode, const float* __restrict__ A,
                                                const float* __restrict__ W,
                                                const float* __restrict__ bias,
                                                float* __restrict__ out) {
    __shared__ uint32_t sAh[16][136], sAl[16][136], sBh[16][136], sBl[16][136];
    const int tid = threadIdx.x;
    const int lane = tid & 31, wid = tid >> 5;
    const int wm = wid >> 1, wn = wid & 1;        // warp tile: rows wm*32, cols wn*64
    const int bn = blockIdx.x, bm = blockIdx.y;

    const int r = tid >> 1;                       // staging row 0..127
    const int kc = (tid & 1) * 8;                 // k sub-offset 0/8

    float c[2][8][4];
    #pragma unroll
    for (int mt = 0; mt < 2; mt++)
        #pragma unroll
        for (int nt = 0; nt < 8; nt++)
            #pragma unroll
            for (int q = 0; q < 4; q++) c[mt][nt][q] = 0.f;

    const float* Bptr = W + (size_t)(bn*128 + r)*DIMC;

    float4 pa[2], pb[2];
    // load tile 0
    {
        const float* Asrc;
        if (mode == 0) Asrc = A + (size_t)(bm*128 + r)*DIMC + kc;
        else {
            int gi = bm*128 + r; int b = gi >> 10, n = gi & 1023;
            Asrc = g_O + (((size_t)b*NH + 0)*SEQ + n)*HD + kc;
        }
        pa[0] = *(const float4*)(Asrc);
        pa[1] = *(const float4*)(Asrc + 4);
        pb[0] = *(const float4*)(Bptr + kc);
        pb[1] = *(const float4*)(Bptr + kc + 4);
    }

    for (int kt = 0; kt < DIMC/16; kt++) {
        __syncthreads();
        // split + stage
        #pragma unroll
        for (int q = 0; q < 8; q++) {
            float av = (q < 4) ? ((const float*)&pa[0])[q] : ((const float*)&pa[1])[q-4];
            float bv = (q < 4) ? ((const float*)&pb[0])[q] : ((const float*)&pb[1])[q-4];
            uint32_t h, l;
            split_tf32(av, h, l);
            sAh[kc+q][r] = h; sAl[kc+q][r] = l;
            split_tf32(bv, h, l);
            sBh[kc+q][r] = h; sBl[kc+q][r] = l;
        }
        __syncthreads();
        // prefetch next
        if (kt + 1 < DIMC/16) {
            const float* Asrc;
            if (mode == 0) Asrc = A + (size_t)(bm*128 + r)*DIMC + (kt+1)*16 + kc;
            else {
                int gi = bm*128 + r; int b = gi >> 10, n = gi & 1023;
                int j0 = (kt+1)*16 + kc;
                Asrc = g_O + (((size_t)b*NH + (j0 >> 6))*SEQ + n)*HD + (j0 & 63);
            }
            pa[0] = *(const float4*)(Asrc);
            pa[1] = *(const float4*)(Asrc + 4);
            pb[0] = *(const float4*)(Bptr + (kt+1)*16 + kc);
            pb[1] = *(const float4*)(Bptr + (kt+1)*16 + kc + 4);
        }
        // compute: 2 k8-steps
        #pragma unroll
        for (int k8 = 0; k8 < 2; k8++) {
            const int kb = k8*8 + (lane & 3);
            uint32_t ah[2][4], al[2][4];
            #pragma unroll
            for (int mt = 0; mt < 2; mt++) {
                int m0 = wm*32 + mt*16 + (lane >> 2);
                ah[mt][0] = sAh[kb][m0];   ah[mt][1] = sAh[kb][m0+8];
                ah[mt][2] = sAh[kb+4][m0]; ah[mt][3] = sAh[kb+4][m0+8];
                al[mt][0] = sAl[kb][m0];   al[mt][1] = sAl[kb][m0+8];
                al[mt][2] = sAl[kb+4][m0]; al[mt][3] = sAl[kb+4][m0+8];
            }
            #pragma unroll
            for (int nt = 0; nt < 8; nt++) {
                int n0 = wn*64 + nt*8 + (lane >> 2);
                uint32_t bh0 = sBh[kb][n0], bh1 = sBh[kb+4][n0];
                uint32_t bl0 = sBl[kb][n0], bl1 = sBl[kb+4][n0];
                #pragma unroll
                for (int mt = 0; mt < 2; mt++) {
                    MMA_TF32(c[mt][nt], ah[mt], bh0, bh1);
                    MMA_TF32(c[mt][nt], al[mt], bh0, bh1);
                    MMA_TF32(c[mt][nt], ah[mt], bl0, bl1);
                }
            }
        }
    }

    // ---- epilogue ----
    #pragma unroll
    for (int mt = 0; mt < 2; mt++) {
        #pragma unroll
        for (int nt = 0; nt < 8; nt++) {
            int gcb = bn*128 + wn*64 + nt*8 + (lane & 3)*2;
            float bs0 = bias[gcb], bs1 = bias[gcb+1];
            #pragma unroll
            for (int half = 0; half < 2; half++) {
                int rowl = wm*32 + mt*16 + (lane >> 2) + half*8;
                int gi = bm*128 + rowl;
                float v0 = c[mt][nt][half*2]   + bs0;
                float v1 = c[mt][nt][half*2+1] + bs1;
                if (mode == 0) {
                    int b = gi >> 10, n = gi & 1023;
                    int t = gcb / DIMC;
                    int r0 = gcb - t*DIMC;
                    int h = r0 >> 6, d = r0 & 63;
                    size_t dst = (((size_t)b*NH + h)*SEQ + n)*HD + d;
                    if (t == 0) { v0 *= 0.125f; v1 *= 0.125f; *(float2*)(g_Q + dst) = make_float2(v0, v1); }
                    else if (t == 1) *(float2*)(g_K + dst) = make_float2(v0, v1);
                    else             *(float2*)(g_V + dst) = make_float2(v0, v1);
                } else {
                    *(float2*)(out + (size_t)gi*DIMC + gcb) = make_float2(v0, v1);
                }
            }
        }
    }
}

// ---------------- 0: zero counters/hists ----------------
__global__ void zero_small() {
    size_t n = (size_t)BH*NBINS;
    for (size_t i = blockIdx.x*(size_t)blockDim.x + threadIdx.x; i < n; i += (size_t)gridDim.x*blockDim.x) {
        g_samphist[i] = 0u; g_hist1[i] = 0u; g_hist2[i] = 0u;
    }
    if (blockIdx.x == 0 && threadIdx.x < BH) {
        g_gcnt[threadIdx.x] = 0u;
        g_cntbelow[threadIdx.x] = 0u;
        g_ok[threadIdx.x] = 0u;
    }
}

// ---------------- score GEMM + exp (unnormalized softmax numerator) ----------------
__global__ void __launch_bounds__(256,2) score_gemm(const float* __restrict__ ts,
                                                    float* __restrict__ P) {
    __shared__ float Asr[16][132];
    __shared__ float Bs[16][132];
    __shared__ float lts[128];

    const int head = blockIdx.z;
    const int b = head / NH;
    const int rb = blockIdx.y, cb = blockIdx.x;
    const int tid = threadIdx.x;
    const int tx = tid & 15, ty = tid >> 4;

    const float* Aptr = g_Q + (size_t)head*SEQ*HD + (size_t)(rb*128)*HD;
    const float* Bptr = g_K + (size_t)head*SEQ*HD + (size_t)(cb*128)*HD;

    if (tid < 128) lts[tid] = logf(ts[b*SEQ + cb*128 + tid]);

    float4 pa[2], pb[2];
    #pragma unroll
    for (int p = 0; p < 2; p++) {
        int f = tid + p*256; int r = f >> 2, kc = (f & 3) << 2;
        pa[p] = *(const float4*)(Aptr + (size_t)r*HD + kc);
        pb[p] = *(const float4*)(Bptr + (size_t)r*HD + kc);
    }

    float acc[8][8];
    #pragma unroll
    for (int i = 0; i < 8; i++)
        #pragma unroll
        for (int j = 0; j < 8; j++) acc[i][j] = 0.f;

    for (int kt = 0; kt < HD/16; kt++) {
        #pragma unroll
        for (int p = 0; p < 2; p++) {
            int f = tid + p*256; int r = f >> 2, kc = (f & 3) << 2;
            Asr[kc+0][r]=pa[p].x; Asr[kc+1][r]=pa[p].y; Asr[kc+2][r]=pa[p].z; Asr[kc+3][r]=pa[p].w;
            Bs[kc+0][r]=pb[p].x;  Bs[kc+1][r]=pb[p].y;  Bs[kc+2][r]=pb[p].z;  Bs[kc+3][r]=pb[p].w;
        }
        __syncthreads();
        if (kt + 1 < HD/16) {
            #pragma unroll
            for (int p = 0; p < 2; p++) {
                int f = tid + p*256; int r = f >> 2, kc = (f & 3) << 2;
                pa[p] = *(const float4*)(Aptr + (size_t)r*HD + (kt+1)*16 + kc);
                pb[p] = *(const float4*)(Bptr + (size_t)r*HD + (kt+1)*16 + kc);
            }
        }
        #pragma unroll
        for (int kk = 0; kk < 16; kk++) {
            float4 a0 = *(const float4*)&Asr[kk][ty*8];
            float4 a1 = *(const float4*)&Asr[kk][ty*8+4];
            float4 b0 = *(const float4*)&Bs[kk][tx*8];
            float4 b1 = *(const float4*)&Bs[kk][tx*8+4];
            float rm[8] = {a0.x,a0.y,a0.z,a0.w,a1.x,a1.y,a1.z,a1.w};
            float rn[8] = {b0.x,b0.y,b0.z,b0.w,b1.x,b1.y,b1.z,b1.w};
            #pragma unroll
            for (int i = 0; i < 8; i++)
                #pragma unroll
                for (int j = 0; j < 8; j++) acc[i][j] += rm[i]*rn[j];
        }
        __syncthreads();
    }

    float rowpart[8];
    #pragma unroll
    for (int i = 0; i < 8; i++) rowpart[i] = 0.f;

    #pragma unroll
    for (int i = 0; i < 8; i++) {
        int r = rb*128 + ty*8 + i;
        float* Pr = P + (size_t)head*NN + (size_t)r*1024 + cb*128 + tx*8;
        float e[8];
        #pragma unroll
        for (int j = 0; j < 8; j++) {
            e[j] = __expf(acc[i][j] + lts[tx*8 + j]);
            rowpart[i] += e[j];
        }
        *(float4*)(Pr)     = make_float4(e[0], e[1], e[2], e[3]);
        *(float4*)(Pr + 4) = make_float4(e[4], e[5], e[6], e[7]);
    }
    #pragma unroll
    for (int i = 0; i < 8; i++) {
        float v = rowpart[i];
        #pragma unroll
        for (int o = 8; o > 0; o >>= 1) v += __shfl_xor_sync(0xffffffffu, v, o);
        if (tx == 0) {
            int r = rb*128 + ty*8 + i;
            g_partial[((size_t)head*SEQ + r)*8 + cb] = v;
        }
    }
}

// ---------------- row inverse sums ----------------
__global__ void __launch_bounds__(1024) rowinv_kernel() {
    const int head = blockIdx.x;
    const int r = threadIdx.x;
    const float* pp = g_partial + ((size_t)head*SEQ + r)*8;
    float s = 0.f;
    #pragma unroll
    for (int j = 0; j < 8; j++) s += pp[j];
    g_inv[(size_t)head*SEQ + r] = 1.0f / s;
}

// ---------------- sampled histogram ----------------
__global__ void __launch_bounds__(256) sample_hist(const float* __restrict__ P) {
    extern __shared__ unsigned sh[];
    const int head = blockIdx.y, q = blockIdx.x;
    const int tid = threadIdx.x, lane = tid & 31;
    for (int i = tid; i < NBINS; i += 256) sh[i] = 0u;
    __syncthreads();
    const float4* base = (const float4*)(P + (size_t)head*NN);
    const float* invh = g_inv + (size_t)head*SEQ;
    for (int it = 0; it < 16; it++) {
        int i = tid + it*256;
        int v = q*65536 + i*16;
        float4 x = base[v];
        float inv = invh[v >> 8];
        float pv[4] = {x.x*inv, x.y*inv, x.z*inv, x.w*inv};
        #pragma unroll
        for (int e = 0; e < 4; e++) {
            unsigned bin = __float_as_uint(pv[e]) >> 15;
            if (bin >= NBINS) bin = NBINS-1;
            unsigned mask = __match_any_sync(0xffffffffu, bin);
            if (lane == (__ffs(mask)-1)) atomicAdd(&sh[bin], (unsigned)__popc(mask));
        }
    }
    __syncthreads();
    unsigned* gh = g_samphist + (size_t)head*NBINS;
    for (int i = tid; i < NBINS; i += 256) {
        unsigned c = sh[i];
        if (c) atomicAdd(&gh[i], c);
    }
}

// ---------------- window selection ----------------
__global__ void __launch_bounds__(256) window_select() {
    const int head = blockIdx.x, tid = threadIdx.x;
    __shared__ unsigned part[256];
    __shared__ unsigned excl[256];
    const unsigned* h = g_samphist + (size_t)head*NBINS;
    unsigned s = 0;
    for (int j = 0; j < 128; j++) s += h[tid*128 + j];
    part[tid] = s;
    __syncthreads();
    if (tid == 0) {
        unsigned c = 0;
        for (int i = 0; i < 256; i++) { excl[i] = c; c += part[i]; }
    }
    __syncthreads();
    unsigned S = excl[255] + part[255];
    unsigned T1 = (SKR > SAMPM) ? (SKR - SAMPM) : 1u;
    unsigned T2 = (SKR + SAMPM < S) ? (SKR + SAMPM) : S;
    unsigned lo = excl[tid], hi = lo + part[tid];
    if (lo < T1 && T1 <= hi) {
        unsigned c = lo;
        for (int j = 0; j < 128; j++) {
            c += h[tid*128 + j];
            if (c >= T1) { g_wlo[head] = tid*128 + j; break; }
        }
    }
    if (lo < T2 && T2 <= hi) {
        unsigned c = lo;
        for (int j = 0; j < 128; j++) {
            c += h[tid*128 + j];
            if (c >= T2) { g_whi[head] = tid*128 + j; break; }
        }
    }
}

// ---------------- exact count-below + gather ----------------
__global__ void __launch_bounds__(512) count_gather(const float* __restrict__ P) {
    __shared__ float sinv[128];
    __shared__ unsigned s_below;
    const int head = blockIdx.y, chunk = blockIdx.x;
    const int tid = threadIdx.x, lane = tid & 31;
    if (tid == 0) s_below = 0;
    if (tid < 128) sinv[tid] = g_inv[(size_t)head*SEQ + chunk*128 + tid];
    __syncthreads();
    const unsigned wlo = g_wlo[head], whi = g_whi[head];
    const float4* base = (const float4*)(P + (size_t)head*NN + (size_t)chunk*131072);
    float* gout = g_gath + (size_t)head*GCAP;
    unsigned below = 0;
    for (int it = 0; it < 64; it++) {
        int v = tid + it*512;
        float4 x = base[v];
        float inv = sinv[v >> 8];
        float pv[4] = {x.x*inv, x.y*inv, x.z*inv, x.w*inv};
        #pragma unroll
        for (int e = 0; e < 4; e++) {
            unsigned bits = __float_as_uint(pv[e]);
            unsigned bin = bits >> 15;
            below += (bin < wlo) ? 1u : 0u;
            bool inw = (bin >= wlo) && (bin <= whi);
            unsigned bal = __ballot_sync(0xffffffffu, inw);
            if (bal) {
                unsigned cnt = __popc(bal);
                unsigned basep = 0;
                if (lane == 0) basep = atomicAdd(&g_gcnt[head], cnt);
                basep = __shfl_sync(0xffffffffu, basep, 0);
                if (inw) {
                    unsigned pos = basep + __popc(bal & ((1u << lane) - 1u));
                    if (pos < GCAP) gout[pos] = pv[e];
                }
            }
        }
    }
    #pragma unroll
    for (int o = 16; o > 0; o >>= 1) below += __shfl_xor_sync(0xffffffffu, below, o);
    if (lane == 0) atomicAdd(&s_below, below);
    __syncthreads();
    if (tid == 0) atomicAdd(&g_cntbelow[head], s_below);
}

// ---------------- verify window ----------------
__global__ void check_ok() {
    int t = threadIdx.x;
    if (t < BH) {
        unsigned cb = g_cntbelow[t];
        unsigned gc = g_gcnt[t];
        bool ok = (gc <= GCAP) && (cb < KTH) && (KTH <= cb + gc);
        g_ok[t] = ok ? 1u : 0u;
    }
}

// ---------------- fallback exact path (early-exit when ok) ----------------
__global__ void __launch_bounds__(512) fb_hist1(const float* __restrict__ P) {
    const int head = blockIdx.y;
    if (g_ok[head]) return;
    extern __shared__ unsigned sh[];
    __shared__ float sinv[128];
    const int chunk = blockIdx.x;
    const int tid = threadIdx.x, lane = tid & 31;
    for (int i = tid; i < NBINS; i += 512) sh[i] = 0u;
    if (tid < 128) sinv[tid] = g_inv[(size_t)head*SEQ + chunk*128 + tid];
    __syncthreads();
    const float4* base = (const float4*)(P + (size_t)head*NN + (size_t)chunk*131072);
    for (int it = 0; it < 64; it++) {
        int v = tid + it*512;
        float4 x = base[v];
        float inv = sinv[v >> 8];
        float pv[4] = {x.x*inv, x.y*inv, x.z*inv, x.w*inv};
        #pragma unroll
        for (int e = 0; e < 4; e++) {
            unsigned bin = __float_as_uint(pv[e]) >> 15;
            if (bin >= NBINS) bin = NBINS-1;
            unsigned mask = __match_any_sync(0xffffffffu, bin);
            if (lane == (__ffs(mask)-1)) atomicAdd(&sh[bin], (unsigned)__popc(mask));
        }
    }
    __syncthreads();
    unsigned* gh = g_hist1 + (size_t)head*NBINS;
    for (int i = tid; i < NBINS; i += 512) {
        unsigned c = sh[i];
        if (c) atomicAdd(&gh[i], c);
    }
}

__global__ void __launch_bounds__(256) fb_select1() {
    const int head = blockIdx.x, tid = threadIdx.x;
    if (g_ok[head]) return;
    __shared__ unsigned part[256];
    __shared__ unsigned excl[256];
    const unsigned* h = g_hist1 + (size_t)head*NBINS;
    unsigned s = 0;
    for (int j = 0; j < 128; j++) s += h[tid*128 + j];
    part[tid] = s;
    __syncthreads();
    if (tid == 0) {
        unsigned c = 0;
        for (int i = 0; i < 256; i++) { excl[i] = c; c += part[i]; }
    }
    __syncthreads();
    unsigned lo = excl[tid], hi = lo + part[tid];
    if (lo < KTH && KTH <= hi) {
        unsigned c = lo;
        for (int j = 0; j < 128; j++) {
            unsigned cnt = h[tid*128 + j];
            if (c + cnt >= KTH) { g_bucket[head] = tid*128 + j; g_rank[head] = KTH - c; break; }
            c += cnt;
        }
    }
}

__global__ void __launch_bounds__(512) fb_hist2(const float* __restrict__ P) {
    const int head = blockIdx.y;
    if (g_ok[head]) return;
    extern __shared__ unsigned sh[];
    __shared__ float sinv[128];
    const int chunk = blockIdx.x;
    const int tid = threadIdx.x, lane = tid & 31;
    for (int i = tid; i < NBINS; i += 512) sh[i] = 0u;
    if (tid < 128) sinv[tid] = g_inv[(size_t)head*SEQ + chunk*128 + tid];
    __syncthreads();
    const unsigned bucket = g_bucket[head];
    const float4* base = (const float4*)(P + (size_t)head*NN + (size_t)chunk*131072);
    for (int it = 0; it < 64; it++) {
        int v = tid + it*512;
        float4 x = base[v];
        float inv = sinv[v >> 8];
        float pv[4] = {x.x*inv, x.y*inv, x.z*inv, x.w*inv};
        #pragma unroll
        for (int e = 0; e < 4; e++) {
            unsigned bits = __float_as_uint(pv[e]);
            unsigned top = bits >> 15;
            bool inb = (top == bucket);
            unsigned bin = inb ? (bits & 0x7FFFu) : 0xFFFFFFFFu;
            unsigned mask = __match_any_sync(0xffffffffu, bin);
            if (inb && lane == (__ffs(mask)-1)) atomicAdd(&sh[bin], (unsigned)__popc(mask));
        }
    }
    __syncthreads();
    unsigned* gh = g_hist2 + (size_t)head*NBINS;
    for (int i = tid; i < NBINS; i += 512) {
        unsigned c = sh[i];
        if (c) atomicAdd(&gh[i], c);
    }
}

__global__ void __launch_bounds__(256) fb_select2() {
    const int head = blockIdx.x, tid = threadIdx.x;
    if (g_ok[head]) return;
    __shared__ unsigned part[256];
    __shared__ unsigned excl[256];
    const unsigned target = g_rank[head];
    const unsigned* h = g_hist2 + (size_t)head*NBINS;
    unsigned s = 0;
    for (int j = 0; j < 128; j++) s += h[tid*128 + j];
    part[tid] = s;
    __syncthreads();
    if (tid == 0) {
        unsigned c = 0;
        for (int i = 0; i < 256; i++) { excl[i] = c; c += part[i]; }
    }
    __syncthreads();
    unsigned lo = excl[tid], hi = lo + part[tid];
    if (lo < target && target <= hi) {
        unsigned c = lo;
        for (int j = 0; j < 128; j++) {
            unsigned cnt = h[tid*128 + j];
            if (c + cnt >= target) {
                unsigned bits = (g_bucket[head] << 15) | (unsigned)(tid*128 + j);
                g_thresh[head] = __uint_as_float(bits);
                break;
            }
            c += cnt;
        }
    }
}

// ---------------- exact 2-level select over gathered values ----------------
__global__ void __launch_bounds__(1024) final_select() {
    const int head = blockIdx.x;
    if (!g_ok[head]) return;
    extern __shared__ unsigned hist[];
    __shared__ unsigned part[1024];
    __shared__ unsigned excl[1024];
    __shared__ unsigned s_bucket, s_t2;
    const int tid = threadIdx.x, lane = tid & 31;
    const unsigned n = g_gcnt[head];
    const unsigned target = KTH - g_cntbelow[head];
    const float* g = g_gath + (size_t)head*GCAP;
    const unsigned ntrip = (n + 1023u) & ~1023u;

    for (int i = tid; i < NBINS; i += 1024) hist[i] = 0u;
    __syncthreads();
    for (unsigned i = tid; i < ntrip; i += 1024) {
        bool valid = (i < n);
        unsigned bin = valid ? (__float_as_uint(g[i]) >> 15) : 0xFFFFFFFFu;
        unsigned mask = __match_any_sync(0xffffffffu, bin);
        if (valid && lane == (__ffs(mask)-1)) atomicAdd(&hist[bin], (unsigned)__popc(mask));
    }
    __syncthreads();
    {
        unsigned s = 0;
        for (int j = 0; j < 32; j++) s += hist[tid*32 + j];
        part[tid] = s;
        __syncthreads();
        if (tid == 0) {
            unsigned c = 0;
            for (int i = 0; i < 1024; i++) { excl[i] = c; c += part[i]; }
        }
        __syncthreads();
        unsigned lo = excl[tid], hi = lo + part[tid];
        if (lo < target && target <= hi) {
            unsigned c = lo;
            for (int j = 0; j < 32; j++) {
                unsigned cnt = hist[tid*32 + j];
                if (c + cnt >= target) { s_bucket = tid*32 + j; s_t2 = target - c; break; }
                c += cnt;
            }
        }
    }
    __syncthreads();
    const unsigned bucket = s_bucket;
    const unsigned t2 = s_t2;
    __syncthreads();
    for (int i = tid; i < NBINS; i += 1024) hist[i] = 0u;
    __syncthreads();
    for (unsigned i = tid; i < ntrip; i += 1024) {
        bool valid = (i < n);
        unsigned bits = valid ? __float_as_uint(g[i]) : 0xFFFFFFFFu;
        bool inb = valid && ((bits >> 15) == bucket);
        unsigned bin = inb ? (bits & 0x7FFFu) : 0xFFFFFFFFu;
        unsigned mask = __match_any_sync(0xffffffffu, bin);
        if (inb && lane == (__ffs(mask)-1)) atomicAdd(&hist[bin], (unsigned)__popc(mask));
    }
    __syncthreads();
    {
        unsigned s = 0;
        for (int j = 0; j < 32; j++) s += hist[tid*32 + j];
        part[tid] = s;
        __syncthreads();
        if (tid == 0) {
            unsigned c = 0;
            for (int i = 0; i < 1024; i++) { excl[i] = c; c += part[i]; }
        }
        __syncthreads();
        unsigned lo = excl[tid], hi = lo + part[tid];
        if (lo < t2 && t2 <= hi) {
            unsigned c = lo;
            for (int j = 0; j < 32; j++) {
                unsigned cnt = hist[tid*32 + j];
                if (c + cnt >= t2) {
                    unsigned bits = (bucket << 15) | (unsigned)(tid*32 + j);
                    g_thresh[head] = __uint_as_float(bits);
                    break;
                }
                c += cnt;
            }
        }
    }
}

// ---------------- normalize + sparsify P + O = P' @ V ----------------
__global__ void __launch_bounds__(256) av_kernel(float* __restrict__ P) {
    __shared__ float Ps[32*132];
    __shared__ float Vs[32*68];
    __shared__ float sinv[128];
    const int head = blockIdx.y, rb = blockIdx.x;
    const int tid = threadIdx.x;
    const int tx = tid & 15, ty = tid >> 4;
    const float t = g_thresh[head];
    float* Pbase = P + (size_t)head*NN + (size_t)rb*128*1024;
    const float* Vbase = g_V + (size_t)head*SEQ*HD;

    if (tid < 128) sinv[tid] = g_inv[(size_t)head*SEQ + rb*128 + tid];

    float acc[8][4];
    #pragma unroll
    for (int i = 0; i < 8; i++)
        #pragma unroll
        for (int j = 0; j < 4; j++) acc[i][j] = 0.f;

    float4 rp[4]; float4 rv[2];
    #pragma unroll
    for (int p = 0; p < 4; p++) {
        int v = tid + p*256; int r = v >> 3, c4 = (v & 7) << 2;
        rp[p] = *(const float4*)(Pbase + (size_t)r*1024 + c4);
    }
    #pragma unroll
    for (int p = 0; p < 2; p++) {
        int v = tid + p*256; int kk = v >> 4, c4 = (v & 15) << 2;
        rv[p] = *(const float4*)(Vbase + (size_t)kk*64 + c4);
    }
    __syncthreads();

    for (int kb = 0; kb < 32; kb++) {
        #pragma unroll
        for (int p = 0; p < 4; p++) {
            int v = tid + p*256; int r = v >> 3, c4 = (v & 7) << 2;
            float inv = sinv[r];
            float4 x = rp[p];
            x.x *= inv; x.y *= inv; x.z *= inv; x.w *= inv;
            x.x = (x.x < t) ? 0.f : x.x;
            x.y = (x.y < t) ? 0.f : x.y;
            x.z = (x.z < t) ? 0.f : x.z;
            x.w = (x.w < t) ? 0.f : x.w;
            *(float4*)(Pbase + (size_t)r*1024 + kb*32 + c4) = x;
            Ps[(c4+0)*132 + r] = x.x;
            Ps[(c4+1)*132 + r] = x.y;
            Ps[(c4+2)*132 + r] = x.z;
            Ps[(c4+3)*132 + r] = x.w;
        }
        #pragma unroll
        for (int p = 0; p < 2; p++) {
            int v = tid + p*256; int kk = v >> 4, c4 = (v & 15) << 2;
            *(float4*)(Vs + kk*68 + c4) = rv[p];
        }
        __syncthreads();
        if (kb + 1 < 32) {
            #pragma unroll
            for (int p = 0; p < 4; p++) {
                int v = tid + p*256; int r = v >> 3, c4 = (v & 7) << 2;
                rp[p] = *(const float4*)(Pbase + (size_t)r*1024 + (kb+1)*32 + c4);
            }
            #pragma unroll
            for (int p = 0; p < 2; p++) {
                int v = tid + p*256; int kk = v >> 4, c4 = (v & 15) << 2;
                rv[p] = *(const float4*)(Vbase + (size_t)((kb+1)*32 + kk)*64 + c4);
            }
        }
        #pragma unroll
        for (int kk = 0; kk < 32; kk++) {
            float4 m0 = *(const float4*)(Ps + kk*132 + ty*8);
            float4 m1 = *(const float4*)(Ps + kk*132 + ty*8 + 4);
            float4 n0 = *(const float4*)(Vs + kk*68 + tx*4);
            float rm[8] = {m0.x,m0.y,m0.z,m0.w,m1.x,m1.y,m1.z,m1.w};
            float rn[4] = {n0.x,n0.y,n0.z,n0.w};
            #pragma unroll
            for (int i = 0; i < 8; i++)
                #pragma unroll
                for (int j = 0; j < 4; j++) acc[i][j] += rm[i]*rn[j];
        }
        __syncthreads();
    }
    float* Obase = g_O + (size_t)head*SEQ*HD + (size_t)(rb*128 + ty*8)*64 + tx*4;
    #pragma unroll
    for (int i = 0; i < 8; i++) {
        float4 o = make_float4(acc[i][0], acc[i][1], acc[i][2], acc[i][3]);
        *(float4*)(Obase + (size_t)i*64) = o;
    }
}

// ---------------- launch ----------------
extern "C" void kernel_launch(void* const* d_in, const int* in_sizes, int n_in,
                              void* d_out, int out_size) {
    const float* x     = (const float*)d_in[0];
    const float* ts    = (const float*)d_in[1];
    const float* wqkv  = (const float*)d_in[2];
    const float* bqkv  = (const float*)d_in[3];
    const float* wproj = (const float*)d_in[4];
    const float* bproj = (const float*)d_in[5];
    float* out = (float*)d_out;

    const size_t out_elems  = (size_t)BATCH*SEQ*DIMC;
    const size_t attn_elems = (size_t)BH*NN;
    float* P;
    if ((size_t)out_size >= out_elems + attn_elems) {
        P = out + out_elems;
    } else {
        cudaGetSymbolAddress((void**)&P, g_Pfallback);
    }

    cudaFuncSetAttribute(sample_hist,  cudaFuncAttributeMaxDynamicSharedMemorySize, NBINS*4);
    cudaFuncSetAttribute(fb_hist1,     cudaFuncAttributeMaxDynamicSharedMemorySize, NBINS*4);
    cudaFuncSetAttribute(fb_hist2,     cudaFuncAttributeMaxDynamicSharedMemorySize, NBINS*4);
    cudaFuncSetAttribute(final_select, cudaFuncAttributeMaxDynamicSharedMemorySize, NBINS*4);

    zero_small<<<1024, 256>>>();
    mma_gemm<<<dim3(2304/128, 8192/128), 256>>>(0, x, wqkv, bqkv, nullptr);
    score_gemm<<<dim3(8, 8, 96), 256>>>(ts, P);
    rowinv_kernel<<<96, 1024>>>();
    sample_hist<<<dim3(4, 96), 256, NBINS*4>>>(P);
    window_select<<<96, 256>>>();
    count_gather<<<dim3(8, 96), 512>>>(P);
    check_ok<<<1, 128>>>();
    fb_hist1<<<dim3(8, 96), 512, NBINS*4>>>(P);
    fb_select1<<<96, 256>>>();
    fb_hist2<<<dim3(8, 96), 512, NBINS*4>>>(P);
    fb_select2<<<96, 256>>>();
    final_select<<<96, 1024, NBINS*4>>>();
    av_kernel<<<dim3(8, 96), 256>>>(P);
    mma_gemm<<<dim3(768/128, 8192/128), 256>>>(1, nullptr, wproj, bproj, out);
}

// round 7
// speedup vs baseline: 1.5695x; 1.0054x over previous
#include <cuda_runtime.h>
#include <math.h>
#include <stdint.h>

#define BATCH 8
#define SEQ   1024
#define DIMC  768
#define NH    12
#define HD    64
#define BH    (BATCH*NH)        // 96
#define NN    (SEQ*SEQ)         // 1048576
#define KTH   524288u
#define NBINS 32768
#define GCAP  131072u
#define SAMPM 2048u
#define SKR   32768u

// ---------------- scratch ----------------
__device__ float g_Q[(size_t)BH*SEQ*HD];
__device__ float g_K[(size_t)BH*SEQ*HD];
__device__ float g_V[(size_t)BH*SEQ*HD];
__device__ float g_O[(size_t)BH*SEQ*HD];
__device__ float g_partial[(size_t)BH*SEQ*8];
__device__ float g_inv[(size_t)BH*SEQ];
__device__ float g_Pfallback[(size_t)BH*NN];
__device__ float g_gath[(size_t)BH*GCAP];
__device__ unsigned g_samphist[(size_t)BH*NBINS];
__device__ unsigned g_hist1[(size_t)BH*NBINS];
__device__ unsigned g_hist2[(size_t)BH*NBINS];
__device__ unsigned g_gcnt[BH];
__device__ unsigned g_cntbelow[BH];
__device__ unsigned g_wlo[BH];
__device__ unsigned g_whi[BH];
__device__ unsigned g_ok[BH];
__device__ unsigned g_bucket[BH];
__device__ unsigned g_rank[BH];
__device__ float    g_thresh[BH];

// ================= tf32 mma helpers =========
__device__ __forceinline__ void split_tf32(float v, uint32_t& hi, uint32_t& lo) {
    asm("cvt.rna.tf32.f32 %0, %1;" : "=r"(hi) : "f"(v));
    float r = v - __uint_as_float(hi);
    asm("cvt.rna.tf32.f32 %0, %1;" : "=r"(lo) : "f"(r));
}
#define MMA_TF32(c, a, b0, b1) \
    asm volatile("mma.sync.aligned.m16n8k8.row.col.f32.tf32.tf32.f32 " \
        "{%0,%1,%2,%3}, {%4,%5,%6,%7}, {%8,%9}, {%0,%1,%2,%3};" \
        : "+f"((c)[0]), "+f"((c)[1]), "+f"((c)[2]), "+f"((c)[3]) \
        : "r"((a)[0]), "r"((a)[1]), "r"((a)[2]), "r"((a)[3]), "r"(b0), "r"(b1))

// smem: 2 buffers x 4 arrays x [16][136] u32 = 69632 B (dynamic)
#define ARR_W   2176            // 16*136
#define BUF_W   (4*ARR_W)       // 8704
#define MMA_SMEM (2*BUF_W*4)

// ---------------- tensor-core GEMM via 3xTF32, double-buffered smem ----------------
// mode 0: A = X (K=768), epilogue scatters to Q/K/V (+bias, Q*0.125)
// mode 1: A = g_O gathered (K=768), epilogue writes out (+bias)
__global__ void __launch_bounds__(256, 1) mma_gemm(int mode, const float* __restrict__ A,
                                                   const float* __restrict__ W,
                                                   const float* __restrict__ bias,
                                                   float* __restrict__ out) {
    extern __shared__ uint32_t smem[];
    const int tid = threadIdx.x;
    const int lane = tid & 31, wid = tid >> 5;
    const int wm = wid >> 1, wn = wid & 1;        // warp tile: rows wm*32, cols wn*64
    const int bn = blockIdx.x, bm = blockIdx.y;

    const int r = tid >> 1;                       // staging row 0..127
    const int kc = (tid & 1) * 8;                 // k sub-offset 0/8

    float c[2][8][4];
    #pragma unroll
    for (int mt = 0; mt < 2; mt++)
        #pragma unroll
        for (int nt = 0; nt < 8; nt++)
            #pragma unroll
            for (int q = 0; q < 4; q++) c[mt][nt][q] = 0.f;

    const float* Bptr = W + (size_t)(bn*128 + r)*DIMC;

    float4 pa[2], pb[2];
    {
        const float* Asrc;
        if (mode == 0) Asrc = A + (size_t)(bm*128 + r)*DIMC + kc;
        else {
            int gi = bm*128 + r; int b = gi >> 10, n = gi & 1023;
            Asrc = g_O + (((size_t)b*NH + 0)*SEQ + n)*HD + kc;
        }
        pa[0] = *(const float4*)(Asrc);
        pa[1] = *(const float4*)(Asrc + 4);
        pb[0] = *(const float4*)(Bptr + kc);
        pb[1] = *(const float4*)(Bptr + kc + 4);
    }

    for (int kt = 0; kt < DIMC/16; kt++) {
        const int bsel = kt & 1;
        uint32_t* sAh = smem + bsel*BUF_W;
        uint32_t* sAl = sAh + ARR_W;
        uint32_t* sBh = sAl + ARR_W;
        uint32_t* sBl = sBh + ARR_W;

        // stage tile kt from regs (writes buffer bsel; other warps may still MMA on bsel^1)
        #pragma unroll
        for (int q = 0; q < 8; q++) {
            float av = (q < 4) ? ((const float*)&pa[0])[q] : ((const float*)&pa[1])[q-4];
            float bv = (q < 4) ? ((const float*)&pb[0])[q] : ((const float*)&pb[1])[q-4];
            uint32_t h, l;
            split_tf32(av, h, l);
            sAh[(kc+q)*136 + r] = h; sAl[(kc+q)*136 + r] = l;
            split_tf32(bv, h, l);
            sBh[(kc+q)*136 + r] = h; sBl[(kc+q)*136 + r] = l;
        }
        __syncthreads();

        // prefetch tile kt+1 into regs (overlaps with MMA below)
        if (kt + 1 < DIMC/16) {
            const float* Asrc;
            if (mode == 0) Asrc = A + (size_t)(bm*128 + r)*DIMC + (kt+1)*16 + kc;
            else {
                int gi = bm*128 + r; int b = gi >> 10, n = gi & 1023;
                int j0 = (kt+1)*16 + kc;
                Asrc = g_O + (((size_t)b*NH + (j0 >> 6))*SEQ + n)*HD + (j0 & 63);
            }
            pa[0] = *(const float4*)(Asrc);
            pa[1] = *(const float4*)(Asrc + 4);
            pb[0] = *(const float4*)(Bptr + (kt+1)*16 + kc);
            pb[1] = *(const float4*)(Bptr + (kt+1)*16 + kc + 4);
        }

        // compute on buffer bsel: 2 k8-steps
        #pragma unroll
        for (int k8 = 0; k8 < 2; k8++) {
            const int kb = k8*8 + (lane & 3);
            uint32_t ah[2][4], al[2][4];
            #pragma unroll
            for (int mt = 0; mt < 2; mt++) {
                int m0 = wm*32 + mt*16 + (lane >> 2);
                ah[mt][0] = sAh[kb*136 + m0];       ah[mt][1] = sAh[kb*136 + m0+8];
                ah[mt][2] = sAh[(kb+4)*136 + m0];   ah[mt][3] = sAh[(kb+4)*136 + m0+8];
                al[mt][0] = sAl[kb*136 + m0];       al[mt][1] = sAl[kb*136 + m0+8];
                al[mt][2] = sAl[(kb+4)*136 + m0];   al[mt][3] = sAl[(kb+4)*136 + m0+8];
            }
            #pragma unroll
            for (int nt = 0; nt < 8; nt++) {
                int n0 = wn*64 + nt*8 + (lane >> 2);
                uint32_t bh0 = sBh[kb*136 + n0], bh1 = sBh[(kb+4)*136 + n0];
                uint32_t bl0 = sBl[kb*136 + n0], bl1 = sBl[(kb+4)*136 + n0];
                #pragma unroll
                for (int mt = 0; mt < 2; mt++) {
                    MMA_TF32(c[mt][nt], ah[mt], bh0, bh1);
                    MMA_TF32(c[mt][nt], al[mt], bh0, bh1);
                    MMA_TF32(c[mt][nt], ah[mt], bl0, bl1);
                }
            }
        }
        // no trailing sync: next iter stages buffer bsel^1 (not read by in-flight MMA)
    }

    // ---- epilogue ----
    #pragma unroll
    for (int mt = 0; mt < 2; mt++) {
        #pragma unroll
        for (int nt = 0; nt < 8; nt++) {
            int gcb = bn*128 + wn*64 + nt*8 + (lane & 3)*2;
            float bs0 = bias[gcb], bs1 = bias[gcb+1];
            #pragma unroll
            for (int half = 0; half < 2; half++) {
                int rowl = wm*32 + mt*16 + (lane >> 2) + half*8;
                int gi = bm*128 + rowl;
                float v0 = c[mt][nt][half*2]   + bs0;
                float v1 = c[mt][nt][half*2+1] + bs1;
                if (mode == 0) {
                    int b = gi >> 10, n = gi & 1023;
                    int t = gcb / DIMC;
                    int r0 = gcb - t*DIMC;
                    int h = r0 >> 6, d = r0 & 63;
                    size_t dst = (((size_t)b*NH + h)*SEQ + n)*HD + d;
                    if (t == 0) { v0 *= 0.125f; v1 *= 0.125f; *(float2*)(g_Q + dst) = make_float2(v0, v1); }
                    else if (t == 1) *(float2*)(g_K + dst) = make_float2(v0, v1);
                    else             *(float2*)(g_V + dst) = make_float2(v0, v1);
                } else {
                    *(float2*)(out + (size_t)gi*DIMC + gcb) = make_float2(v0, v1);
                }
            }
        }
    }
}

// ---------------- zero kernels (split 3-way so mma_gemm is the 4th launch for ncu) ----
__global__ void zero_h1() {
    size_t n = (size_t)BH*NBINS;
    for (size_t i = blockIdx.x*(size_t)blockDim.x + threadIdx.x; i < n; i += (size_t)gridDim.x*blockDim.x) {
        g_samphist[i] = 0u; g_hist1[i] = 0u;
    }
}
__global__ void zero_h2() {
    size_t n = (size_t)BH*NBINS;
    for (size_t i = blockIdx.x*(size_t)blockDim.x + threadIdx.x; i < n; i += (size_t)gridDim.x*blockDim.x) {
        g_hist2[i] = 0u;
    }
}
__global__ void zero_cnt() {
    if (threadIdx.x < BH) {
        g_gcnt[threadIdx.x] = 0u;
        g_cntbelow[threadIdx.x] = 0u;
        g_ok[threadIdx.x] = 0u;
    }
}

// ---------------- score GEMM + exp (unnormalized softmax numerator) ----------------
__global__ void __launch_bounds__(256,2) score_gemm(const float* __restrict__ ts,
                                                    float* __restrict__ P) {
    __shared__ float Asr[16][132];
    __shared__ float Bs[16][132];
    __shared__ float lts[128];

    const int head = blockIdx.z;
    const int b = head / NH;
    const int rb = blockIdx.y, cb = blockIdx.x;
    const int tid = threadIdx.x;
    const int tx = tid & 15, ty = tid >> 4;

    const float* Aptr = g_Q + (size_t)head*SEQ*HD + (size_t)(rb*128)*HD;
    const float* Bptr = g_K + (size_t)head*SEQ*HD + (size_t)(cb*128)*HD;

    if (tid < 128) lts[tid] = logf(ts[b*SEQ + cb*128 + tid]);

    float4 pa[2], pb[2];
    #pragma unroll
    for (int p = 0; p < 2; p++) {
        int f = tid + p*256; int r = f >> 2, kc = (f & 3) << 2;
        pa[p] = *(const float4*)(Aptr + (size_t)r*HD + kc);
        pb[p] = *(const float4*)(Bptr + (size_t)r*HD + kc);
    }

    float acc[8][8];
    #pragma unroll
    for (int i = 0; i < 8; i++)
        #pragma unroll
        for (int j = 0; j < 8; j++) acc[i][j] = 0.f;

    for (int kt = 0; kt < HD/16; kt++) {
        #pragma unroll
        for (int p = 0; p < 2; p++) {
            int f = tid + p*256; int r = f >> 2, kc = (f & 3) << 2;
            Asr[kc+0][r]=pa[p].x; Asr[kc+1][r]=pa[p].y; Asr[kc+2][r]=pa[p].z; Asr[kc+3][r]=pa[p].w;
            Bs[kc+0][r]=pb[p].x;  Bs[kc+1][r]=pb[p].y;  Bs[kc+2][r]=pb[p].z;  Bs[kc+3][r]=pb[p].w;
        }
        __syncthreads();
        if (kt + 1 < HD/16) {
            #pragma unroll
            for (int p = 0; p < 2; p++) {
                int f = tid + p*256; int r = f >> 2, kc = (f & 3) << 2;
                pa[p] = *(const float4*)(Aptr + (size_t)r*HD + (kt+1)*16 + kc);
                pb[p] = *(const float4*)(Bptr + (size_t)r*HD + (kt+1)*16 + kc);
            }
        }
        #pragma unroll
        for (int kk = 0; kk < 16; kk++) {
            float4 a0 = *(const float4*)&Asr[kk][ty*8];
            float4 a1 = *(const float4*)&Asr[kk][ty*8+4];
            float4 b0 = *(const float4*)&Bs[kk][tx*8];
            float4 b1 = *(const float4*)&Bs[kk][tx*8+4];
            float rm[8] = {a0.x,a0.y,a0.z,a0.w,a1.x,a1.y,a1.z,a1.w};
            float rn[8] = {b0.x,b0.y,b0.z,b0.w,b1.x,b1.y,b1.z,b1.w};
            #pragma unroll
            for (int i = 0; i < 8; i++)
                #pragma unroll
                for (int j = 0; j < 8; j++) acc[i][j] += rm[i]*rn[j];
        }
        __syncthreads();
    }

    float rowpart[8];
    #pragma unroll
    for (int i = 0; i < 8; i++) rowpart[i] = 0.f;

    #pragma unroll
    for (int i = 0; i < 8; i++) {
        int r = rb*128 + ty*8 + i;
        float* Pr = P + (size_t)head*NN + (size_t)r*1024 + cb*128 + tx*8;
        float e[8];
        #pragma unroll
        for (int j = 0; j < 8; j++) {
            e[j] = __expf(acc[i][j] + lts[tx*8 + j]);
            rowpart[i] += e[j];
        }
        *(float4*)(Pr)     = make_float4(e[0], e[1], e[2], e[3]);
        *(float4*)(Pr + 4) = make_float4(e[4], e[5], e[6], e[7]);
    }
    #pragma unroll
    for (int i = 0; i < 8; i++) {
        float v = rowpart[i];
        #pragma unroll
        for (int o = 8; o > 0; o >>= 1) v += __shfl_xor_sync(0xffffffffu, v, o);
        if (tx == 0) {
            int r = rb*128 + ty*8 + i;
            g_partial[((size_t)head*SEQ + r)*8 + cb] = v;
        }
    }
}

// ---------------- row inverse sums ----------------
__global__ void __launch_bounds__(1024) rowinv_kernel() {
    const int head = blockIdx.x;
    const int r = threadIdx.x;
    const float* pp = g_partial + ((size_t)head*SEQ + r)*8;
    float s = 0.f;
    #pragma unroll
    for (int j = 0; j < 8; j++) s += pp[j];
    g_inv[(size_t)head*SEQ + r] = 1.0f / s;
}

// ---------------- sampled histogram ----------------
__global__ void __launch_bounds__(256) sample_hist(const float* __restrict__ P) {
    extern __shared__ unsigned sh[];
    const int head = blockIdx.y, q = blockIdx.x;
    const int tid = threadIdx.x, lane = tid & 31;
    for (int i = tid; i < NBINS; i += 256) sh[i] = 0u;
    __syncthreads();
    const float4* base = (const float4*)(P + (size_t)head*NN);
    const float* invh = g_inv + (size_t)head*SEQ;
    for (int it = 0; it < 16; it++) {
        int i = tid + it*256;
        int v = q*65536 + i*16;
        float4 x = base[v];
        float inv = invh[v >> 8];
        float pv[4] = {x.x*inv, x.y*inv, x.z*inv, x.w*inv};
        #pragma unroll
        for (int e = 0; e < 4; e++) {
            unsigned bin = __float_as_uint(pv[e]) >> 15;
            if (bin >= NBINS) bin = NBINS-1;
            unsigned mask = __match_any_sync(0xffffffffu, bin);
            if (lane == (__ffs(mask)-1)) atomicAdd(&sh[bin], (unsigned)__popc(mask));
        }
    }
    __syncthreads();
    unsigned* gh = g_samphist + (size_t)head*NBINS;
    for (int i = tid; i < NBINS; i += 256) {
        unsigned c = sh[i];
        if (c) atomicAdd(&gh[i], c);
    }
}

// ---------------- window selection ----------------
__global__ void __launch_bounds__(256) window_select() {
    const int head = blockIdx.x, tid = threadIdx.x;
    __shared__ unsigned part[256];
    __shared__ unsigned excl[256];
    const unsigned* h = g_samphist + (size_t)head*NBINS;
    unsigned s = 0;
    for (int j = 0; j < 128; j++) s += h[tid*128 + j];
    part[tid] = s;
    __syncthreads();
    if (tid == 0) {
        unsigned c = 0;
        for (int i = 0; i < 256; i++) { excl[i] = c; c += part[i]; }
    }
    __syncthreads();
    unsigned S = excl[255] + part[255];
    unsigned T1 = (SKR > SAMPM) ? (SKR - SAMPM) : 1u;
    unsigned T2 = (SKR + SAMPM < S) ? (SKR + SAMPM) : S;
    unsigned lo = excl[tid], hi = lo + part[tid];
    if (lo < T1 && T1 <= hi) {
        unsigned c = lo;
        for (int j = 0; j < 128; j++) {
            c += h[tid*128 + j];
            if (c >= T1) { g_wlo[head] = tid*128 + j; break; }
        }
    }
    if (lo < T2 && T2 <= hi) {
        unsigned c = lo;
        for (int j = 0; j < 128; j++) {
            c += h[tid*128 + j];
            if (c >= T2) { g_whi[head] = tid*128 + j; break; }
        }
    }
}

// ---------------- exact count-below + gather ----------------
__global__ void __launch_bounds__(512) count_gather(const float* __restrict__ P) {
    __shared__ float sinv[128];
    __shared__ unsigned s_below;
    const int head = blockIdx.y, chunk = blockIdx.x;
    const int tid = threadIdx.x, lane = tid & 31;
    if (tid == 0) s_below = 0;
    if (tid < 128) sinv[tid] = g_inv[(size_t)head*SEQ + chunk*128 + tid];
    __syncthreads();
    const unsigned wlo = g_wlo[head], whi = g_whi[head];
    const float4* base = (const float4*)(P + (size_t)head*NN + (size_t)chunk*131072);
    float* gout = g_gath + (size_t)head*GCAP;
    unsigned below = 0;
    for (int it = 0; it < 64; it++) {
        int v = tid + it*512;
        float4 x = base[v];
        float inv = sinv[v >> 8];
        float pv[4] = {x.x*inv, x.y*inv, x.z*inv, x.w*inv};
        #pragma unroll
        for (int e = 0; e < 4; e++) {
            unsigned bits = __float_as_uint(pv[e]);
            unsigned bin = bits >> 15;
            below += (bin < wlo) ? 1u : 0u;
            bool inw = (bin >= wlo) && (bin <= whi);
            unsigned bal = __ballot_sync(0xffffffffu, inw);
            if (bal) {
                unsigned cnt = __popc(bal);
                unsigned basep = 0;
                if (lane == 0) basep = atomicAdd(&g_gcnt[head], cnt);
                basep = __shfl_sync(0xffffffffu, basep, 0);
                if (inw) {
                    unsigned pos = basep + __popc(bal & ((1u << lane) - 1u));
                    if (pos < GCAP) gout[pos] = pv[e];
                }
            }
        }
    }
    #pragma unroll
    for (int o = 16; o > 0; o >>= 1) below += __shfl_xor_sync(0xffffffffu, below, o);
    if (lane == 0) atomicAdd(&s_below, below);
    __syncthreads();
    if (tid == 0) atomicAdd(&g_cntbelow[head], s_below);
}

// ---------------- verify window ----------------
__global__ void check_ok() {
    int t = threadIdx.x;
    if (t < BH) {
        unsigned cb = g_cntbelow[t];
        unsigned gc = g_gcnt[t];
        bool ok = (gc <= GCAP) && (cb < KTH) && (KTH <= cb + gc);
        g_ok[t] = ok ? 1u : 0u;
    }
}

// ---------------- fallback exact path (early-exit when ok) ----------------
__global__ void __launch_bounds__(512) fb_hist1(const float* __restrict__ P) {
    const int head = blockIdx.y;
    if (g_ok[head]) return;
    extern __shared__ unsigned sh[];
    __shared__ float sinv[128];
    const int chunk = blockIdx.x;
    const int tid = threadIdx.x, lane = tid & 31;
    for (int i = tid; i < NBINS; i += 512) sh[i] = 0u;
    if (tid < 128) sinv[tid] = g_inv[(size_t)head*SEQ + chunk*128 + tid];
    __syncthreads();
    const float4* base = (const float4*)(P + (size_t)head*NN + (size_t)chunk*131072);
    for (int it = 0; it < 64; it++) {
        int v = tid + it*512;
        float4 x = base[v];
        float inv = sinv[v >> 8];
        float pv[4] = {x.x*inv, x.y*inv, x.z*inv, x.w*inv};
        #pragma unroll
        for (int e = 0; e < 4; e++) {
            unsigned bin = __float_as_uint(pv[e]) >> 15;
            if (bin >= NBINS) bin = NBINS-1;
            unsigned mask = __match_any_sync(0xffffffffu, bin);
            if (lane == (__ffs(mask)-1)) atomicAdd(&sh[bin], (unsigned)__popc(mask));
        }
    }
    __syncthreads();
    unsigned* gh = g_hist1 + (size_t)head*NBINS;
    for (int i = tid; i < NBINS; i += 512) {
        unsigned c = sh[i];
        if (c) atomicAdd(&gh[i], c);
    }
}

__global__ void __launch_bounds__(256) fb_select1() {
    const int head = blockIdx.x, tid = threadIdx.x;
    if (g_ok[head]) return;
    __shared__ unsigned part[256];
    __shared__ unsigned excl[256];
    const unsigned* h = g_hist1 + (size_t)head*NBINS;
    unsigned s = 0;
    for (int j = 0; j < 128; j++) s += h[tid*128 + j];
    part[tid] = s;
    __syncthreads();
    if (tid == 0) {
        unsigned c = 0;
        for (int i = 0; i < 256; i++) { excl[i] = c; c += part[i]; }
    }
    __syncthreads();
    unsigned lo = excl[tid], hi = lo + part[tid];
    if (lo < KTH && KTH <= hi) {
        unsigned c = lo;
        for (int j = 0; j < 128; j++) {
            unsigned cnt = h[tid*128 + j];
            if (c + cnt >= KTH) { g_bucket[head] = tid*128 + j; g_rank[head] = KTH - c; break; }
            c += cnt;
        }
    }
}

__global__ void __launch_bounds__(512) fb_hist2(const float* __restrict__ P) {
    const int head = blockIdx.y;
    if (g_ok[head]) return;
    extern __shared__ unsigned sh[];
    __shared__ float sinv[128];
    const int chunk = blockIdx.x;
    const int tid = threadIdx.x, lane = tid & 31;
    for (int i = tid; i < NBINS; i += 512) sh[i] = 0u;
    if (tid < 128) sinv[tid] = g_inv[(size_t)head*SEQ + chunk*128 + tid];
    __syncthreads();
    const unsigned bucket = g_bucket[head];
    const float4* base = (const float4*)(P + (size_t)head*NN + (size_t)chunk*131072);
    for (int it = 0; it < 64; it++) {
        int v = tid + it*512;
        float4 x = base[v];
        float inv = sinv[v >> 8];
        float pv[4] = {x.x*inv, x.y*inv, x.z*inv, x.w*inv};
        #pragma unroll
        for (int e = 0; e < 4; e++) {
            unsigned bits = __float_as_uint(pv[e]);
            unsigned top = bits >> 15;
            bool inb = (top == bucket);
            unsigned bin = inb ? (bits & 0x7FFFu) : 0xFFFFFFFFu;
            unsigned mask = __match_any_sync(0xffffffffu, bin);
            if (inb && lane == (__ffs(mask)-1)) atomicAdd(&sh[bin], (unsigned)__popc(mask));
        }
    }
    __syncthreads();
    unsigned* gh = g_hist2 + (size_t)head*NBINS;
    for (int i = tid; i < NBINS; i += 512) {
        unsigned c = sh[i];
        if (c) atomicAdd(&gh[i], c);
    }
}

__global__ void __launch_bounds__(256) fb_select2() {
    const int head = blockIdx.x, tid = threadIdx.x;
    if (g_ok[head]) return;
    __shared__ unsigned part[256];
    __shared__ unsigned excl[256];
    const unsigned target = g_rank[head];
    const unsigned* h = g_hist2 + (size_t)head*NBINS;
    unsigned s = 0;
    for (int j = 0; j < 128; j++) s += h[tid*128 + j];
    part[tid] = s;
    __syncthreads();
    if (tid == 0) {
        unsigned c = 0;
        for (int i = 0; i < 256; i++) { excl[i] = c; c += part[i]; }
    }
    __syncthreads();
    unsigned lo = excl[tid], hi = lo + part[tid];
    if (lo < target && target <= hi) {
        unsigned c = lo;
        for (int j = 0; j < 128; j++) {
            unsigned cnt = h[tid*128 + j];
            if (c + cnt >= target) {
                unsigned bits = (g_bucket[head] << 15) | (unsigned)(tid*128 + j);
                g_thresh[head] = __uint_as_float(bits);
                break;
            }
            c += cnt;
        }
    }
}

// ---------------- exact 2-level select over gathered values ----------------
__global__ void __launch_bounds__(1024) final_select() {
    const int head = blockIdx.x;
    if (!g_ok[head]) return;
    extern __shared__ unsigned hist[];
    __shared__ unsigned part[1024];
    __shared__ unsigned excl[1024];
    __shared__ unsigned s_bucket, s_t2;
    const int tid = threadIdx.x, lane = tid & 31;
    const unsigned n = g_gcnt[head];
    const unsigned target = KTH - g_cntbelow[head];
    const float* g = g_gath + (size_t)head*GCAP;
    const unsigned ntrip = (n + 1023u) & ~1023u;

    for (int i = tid; i < NBINS; i += 1024) hist[i] = 0u;
    __syncthreads();
    for (unsigned i = tid; i < ntrip; i += 1024) {
        bool valid = (i < n);
        unsigned bin = valid ? (__float_as_uint(g[i]) >> 15) : 0xFFFFFFFFu;
        unsigned mask = __match_any_sync(0xffffffffu, bin);
        if (valid && lane == (__ffs(mask)-1)) atomicAdd(&hist[bin], (unsigned)__popc(mask));
    }
    __syncthreads();
    {
        unsigned s = 0;
        for (int j = 0; j < 32; j++) s += hist[tid*32 + j];
        part[tid] = s;
        __syncthreads();
        if (tid == 0) {
            unsigned c = 0;
            for (int i = 0; i < 1024; i++) { excl[i] = c; c += part[i]; }
        }
        __syncthreads();
        unsigned lo = excl[tid], hi = lo + part[tid];
        if (lo < target && target <= hi) {
            unsigned c = lo;
            for (int j = 0; j < 32; j++) {
                unsigned cnt = hist[tid*32 + j];
                if (c + cnt >= target) { s_bucket = tid*32 + j; s_t2 = target - c; break; }
                c += cnt;
            }
        }
    }
    __syncthreads();
    const unsigned bucket = s_bucket;
    const unsigned t2 = s_t2;
    __syncthreads();
    for (int i = tid; i < NBINS; i += 1024) hist[i] = 0u;
    __syncthreads();
    for (unsigned i = tid; i < ntrip; i += 1024) {
        bool valid = (i < n);
        unsigned bits = valid ? __float_as_uint(g[i]) : 0xFFFFFFFFu;
        bool inb = valid && ((bits >> 15) == bucket);
        unsigned bin = inb ? (bits & 0x7FFFu) : 0xFFFFFFFFu;
        unsigned mask = __match_any_sync(0xffffffffu, bin);
        if (inb && lane == (__ffs(mask)-1)) atomicAdd(&hist[bin], (unsigned)__popc(mask));
    }
    __syncthreads();
    {
        unsigned s = 0;
        for (int j = 0; j < 32; j++) s += hist[tid*32 + j];
        part[tid] = s;
        __syncthreads();
        if (tid == 0) {
            unsigned c = 0;
            for (int i = 0; i < 1024; i++) { excl[i] = c; c += part[i]; }
        }
        __syncthreads();
        unsigned lo = excl[tid], hi = lo + part[tid];
        if (lo < t2 && t2 <= hi) {
            unsigned c = lo;
            for (int j = 0; j < 32; j++) {
                unsigned cnt = hist[tid*32 + j];
                if (c + cnt >= t2) {
                    unsigned bits = (bucket << 15) | (unsigned)(tid*32 + j);
                    g_thresh[head] = __uint_as_float(bits);
                    break;
                }
                c += cnt;
            }
        }
    }
}

// ---------------- normalize + sparsify P + O = P' @ V ----------------
__global__ void __launch_bounds__(256) av_kernel(float* __restrict__ P) {
    __shared__ float Ps[32*132];
    __shared__ float Vs[32*68];
    __shared__ float sinv[128];
    const int head = blockIdx.y, rb = blockIdx.x;
    const int tid = threadIdx.x;
    const int tx = tid & 15, ty = tid >> 4;
    const float t = g_thresh[head];
    float* Pbase = P + (size_t)head*NN + (size_t)rb*128*1024;
    const float* Vbase = g_V + (size_t)head*SEQ*HD;

    if (tid < 128) sinv[tid] = g_inv[(size_t)head*SEQ + rb*128 + tid];

    float acc[8][4];
    #pragma unroll
    for (int i = 0; i < 8; i++)
        #pragma unroll
        for (int j = 0; j < 4; j++) acc[i][j] = 0.f;

    float4 rp[4]; float4 rv[2];
    #pragma unroll
    for (int p = 0; p < 4; p++) {
        int v = tid + p*256; int r = v >> 3, c4 = (v & 7) << 2;
        rp[p] = *(const float4*)(Pbase + (size_t)r*1024 + c4);
    }
    #pragma unroll
    for (int p = 0; p < 2; p++) {
        int v = tid + p*256; int kk = v >> 4, c4 = (v & 15) << 2;
        rv[p] = *(const float4*)(Vbase + (size_t)kk*64 + c4);
    }
    __syncthreads();

    for (int kb = 0; kb < 32; kb++) {
        #pragma unroll
        for (int p = 0; p < 4; p++) {
            int v = tid + p*256; int r = v >> 3, c4 = (v & 7) << 2;
            float inv = sinv[r];
            float4 x = rp[p];
            x.x *= inv; x.y *= inv; x.z *= inv; x.w *= inv;
            x.x = (x.x < t) ? 0.f : x.x;
            x.y = (x.y < t) ? 0.f : x.y;
            x.z = (x.z < t) ? 0.f : x.z;
            x.w = (x.w < t) ? 0.f : x.w;
            *(float4*)(Pbase + (size_t)r*1024 + kb*32 + c4) = x;
            Ps[(c4+0)*132 + r] = x.x;
            Ps[(c4+1)*132 + r] = x.y;
            Ps[(c4+2)*132 + r] = x.z;
            Ps[(c4+3)*132 + r] = x.w;
        }
        #pragma unroll
        for (int p = 0; p < 2; p++) {
            int v = tid + p*256; int kk = v >> 4, c4 = (v & 15) << 2;
            *(float4*)(Vs + kk*68 + c4) = rv[p];
        }
        __syncthreads();
        if (kb + 1 < 32) {
            #pragma unroll
            for (int p = 0; p < 4; p++) {
                int v = tid + p*256; int r = v >> 3, c4 = (v & 7) << 2;
                rp[p] = *(const float4*)(Pbase + (size_t)r*1024 + (kb+1)*32 + c4);
            }
            #pragma unroll
            for (int p = 0; p < 2; p++) {
                int v = tid + p*256; int kk = v >> 4, c4 = (v & 15) << 2;
                rv[p] = *(const float4*)(Vbase + (size_t)((kb+1)*32 + kk)*64 + c4);
            }
        }
        #pragma unroll
        for (int kk = 0; kk < 32; kk++) {
            float4 m0 = *(const float4*)(Ps + kk*132 + ty*8);
            float4 m1 = *(const float4*)(Ps + kk*132 + ty*8 + 4);
            float4 n0 = *(const float4*)(Vs + kk*68 + tx*4);
            float rm[8] = {m0.x,m0.y,m0.z,m0.w,m1.x,m1.y,m1.z,m1.w};
            float rn[4] = {n0.x,n0.y,n0.z,n0.w};
            #pragma unroll
            for (int i = 0; i < 8; i++)
                #pragma unroll
                for (int j = 0; j < 4; j++) acc[i][j] += rm[i]*rn[j];
        }
        __syncthreads();
    }
    float* Obase = g_O + (size_t)head*SEQ*HD + (size_t)(rb*128 + ty*8)*64 + tx*4;
    #pragma unroll
    for (int i = 0; i < 8; i++) {
        float4 o = make_float4(acc[i][0], acc[i][1], acc[i][2], acc[i][3]);
        *(float4*)(Obase + (size_t)i*64) = o;
    }
}

// ---------------- launch ----------------
extern "C" void kernel_launch(void* const* d_in, const int* in_sizes, int n_in,
                              void* d_out, int out_size) {
    const float* x     = (const float*)d_in[0];
    const float* ts    = (const float*)d_in[1];
    const float* wqkv  = (const float*)d_in[2];
    const float* bqkv  = (const float*)d_in[3];
    const float* wproj = (const float*)d_in[4];
    const float* bproj = (const float*)d_in[5];
    float* out = (float*)d_out;

    const size_t out_elems  = (size_t)BATCH*SEQ*DIMC;
    const size_t attn_elems = (size_t)BH*NN;
    float* P;
    if ((size_t)out_size >= out_elems + attn_elems) {
        P = out + out_elems;
    } else {
        cudaGetSymbolAddress((void**)&P, g_Pfallback);
    }

    cudaFuncSetAttribute(mma_gemm,     cudaFuncAttributeMaxDynamicSharedMemorySize, MMA_SMEM);
    cudaFuncSetAttribute(sample_hist,  cudaFuncAttributeMaxDynamicSharedMemorySize, NBINS*4);
    cudaFuncSetAttribute(fb_hist1,     cudaFuncAttributeMaxDynamicSharedMemorySize, NBINS*4);
    cudaFuncSetAttribute(fb_hist2,     cudaFuncAttributeMaxDynamicSharedMemorySize, NBINS*4);
    cudaFuncSetAttribute(final_select, cudaFuncAttributeMaxDynamicSharedMemorySize, NBINS*4);

    zero_h1<<<512, 256>>>();
    zero_h2<<<512, 256>>>();
    zero_cnt<<<1, 128>>>();
    mma_gemm<<<dim3(2304/128, 8192/128), 256, MMA_SMEM>>>(0, x, wqkv, bqkv, nullptr);  // 4th launch -> ncu
    score_gemm<<<dim3(8, 8, 96), 256>>>(ts, P);
    rowinv_kernel<<<96, 1024>>>();
    sample_hist<<<dim3(4, 96), 256, NBINS*4>>>(P);
    window_select<<<96, 256>>>();
    count_gather<<<dim3(8, 96), 512>>>(P);
    check_ok<<<1, 128>>>();
    fb_hist1<<<dim3(8, 96), 512, NBINS*4>>>(P);
    fb_select1<<<96, 256>>>();
    fb_hist2<<<dim3(8, 96), 512, NBINS*4>>>(P);
    fb_select2<<<96, 256>>>();
    final_select<<<96, 1024, NBINS*4>>>();
    av_kernel<<<dim3(8, 96), 256>>>(P);
    mma_gemm<<<dim3(768/128, 8192/128), 256, MMA_SMEM>>>(1, nullptr, wproj, bproj, out);
}